// round 9
// baseline (speedup 1.0000x reference)
#include <cuda_runtime.h>
#include <cuda_bf16.h>

#define NEG    0.2f
#define BNS    0.9999950000374997f   /* 1/sqrt(1+1e-5) */
#define LNEPS  1e-5f
#define B_     16
#define N_     2048
#define KNN    20

#define KCH   32                     /* K chunk */
#define STG   40960                  /* bytes per double-buffer stage */
#define SMEMB 81920
#define NTRI  136                    /* 16*17/2 upper-triangle tiles */

/* ------------- scratch (device globals; no runtime allocation) ------------- */
__device__ float g_xt  [B_*N_*3];
__device__ float g_cat [(size_t)B_*N_*512];
__device__ float g_x5  [(size_t)B_*N_*1024];
__device__ unsigned g_pd [(size_t)B_*N_*N_];      /* transformed order keys */
__device__ float g_xx  [B_*N_];
__device__ int   g_idx [B_*N_*KNN];
__device__ float g_sc  [B_*N_*4];
__device__ float g_att [B_*4096];
__device__ float g_attln[B_*4096];
__device__ float g_y1  [B_*512];
__device__ float g_y2  [B_*256];
__device__ __nv_bfloat16 g_xth[B_*N_*16];
__device__ __nv_bfloat16 g_xtl[B_*N_*16];
__device__ __nv_bfloat16 g_hh [(size_t)B_*N_*256];
__device__ __nv_bfloat16 g_hl [(size_t)B_*N_*256];
__device__ __nv_bfloat16 g_cath[(size_t)B_*N_*512];
__device__ __nv_bfloat16 g_catl[(size_t)B_*N_*512];

__device__ __forceinline__ float lrelu(float v){ return v > 0.f ? v : NEG*v; }
__device__ __forceinline__ unsigned mkkey(float v){
    unsigned u = __float_as_uint(v);
    return (u & 0x80000000u) ? ~u : (u | 0x80000000u);
}

__device__ __forceinline__ unsigned smem_u32(const void* p){
    unsigned a;
    asm("{ .reg .u64 t; cvta.to.shared.u64 t, %1; cvt.u32.u64 %0, t; }":"=r"(a):"l"(p));
    return a;
}
#define LDMX4(r0,r1,r2,r3,a) \
    asm volatile("ldmatrix.sync.aligned.m8n8.x4.shared.b16 {%0,%1,%2,%3}, [%4];" \
        : "=r"(r0),"=r"(r1),"=r"(r2),"=r"(r3) : "r"(a))

__device__ __forceinline__ void mma_bf16(float* c, unsigned a0,unsigned a1,unsigned a2,unsigned a3,
                                         unsigned b0,unsigned b1){
    asm volatile("mma.sync.aligned.m16n8k16.row.col.f32.bf16.bf16.f32 "
        "{%0,%1,%2,%3},{%4,%5,%6,%7},{%8,%9},{%0,%1,%2,%3};"
        : "+f"(c[0]),"+f"(c[1]),"+f"(c[2]),"+f"(c[3])
        : "r"(a0),"r"(a1),"r"(a2),"r"(a3),"r"(b0),"r"(b1));
}
__device__ __forceinline__ unsigned pack2(__nv_bfloat16 a, __nv_bfloat16 b){
    return (unsigned)__bfloat16_as_ushort(a) | ((unsigned)__bfloat16_as_ushort(b)<<16);
}

/* bf16 tile loader: 128 rows x 32 cols into smem, row pitch 80B */
__device__ __forceinline__ void ld_tile_bf16(char* sm, int off,
        const __nv_bfloat16* __restrict__ src, int row0, int rsIn, int k0, int Kpad, int tid){
    for(int i=tid;i<512;i+=256){
        int r=i>>2, q=i&3, k=k0+q*8;
        uint4 v = make_uint4(0,0,0,0);
        if(k < Kpad) v = *(const uint4*)(src + (size_t)(row0+r)*rsIn + k);
        *(uint4*)(sm + off + r*80 + q*16) = v;
    }
}
/* fp32 W loader with on-the-fly hi/lo split */
__device__ __forceinline__ void ld_tile_w(char* sm, int offH, int offL,
        const float* __restrict__ W, int o0, int O, int C2, int k0, int tid){
    for(int i=tid;i<512;i+=256){
        int r=i>>2, q=i&3, o=o0+r, kb=k0+q*8;
        unsigned hu[4], lu[4];
        #pragma unroll
        for(int t=0;t<8;t+=2){
            float v0 = (o<O && kb+t   < C2) ? W[(size_t)o*C2 + kb+t  ] : 0.f;
            float v1 = (o<O && kb+t+1 < C2) ? W[(size_t)o*C2 + kb+t+1] : 0.f;
            __nv_bfloat16 h0=__float2bfloat16(v0), h1=__float2bfloat16(v1);
            __nv_bfloat16 l0=__float2bfloat16(v0-__bfloat162float(h0));
            __nv_bfloat16 l1=__float2bfloat16(v1-__bfloat162float(h1));
            hu[t>>1]=pack2(h0,h1); lu[t>>1]=pack2(l0,l1);
        }
        int so = r*80 + q*16;
        *(uint4*)(sm + offH + so) = make_uint4(hu[0],hu[1],hu[2],hu[3]);
        *(uint4*)(sm + offL + so) = make_uint4(lu[0],lu[1],lu[2],lu[3]);
    }
}

/* one K-chunk (32) of split-precision mma */
__device__ __forceinline__ void gemm_chunk(float (&acc)[4][4][4], unsigned base,
                                           int wm, int wn, int lane){
    int g = lane>>3, r = lane&7;
    #pragma unroll
    for(int h=0;h<2;h++){
        int k16 = h*16;
        unsigned ah[4][4], bh[4][2], bl[4][2];
        #pragma unroll
        for(int mt=0;mt<4;mt++){
            unsigned ad = base + (unsigned)((wm+mt*16+(g&1)*8+r)*80 + (k16+(g>>1)*8)*2);
            LDMX4(ah[mt][0],ah[mt][1],ah[mt][2],ah[mt][3], ad);
        }
        #pragma unroll
        for(int p=0;p<2;p++){
            unsigned bd = base + 20480u + (unsigned)((wn+p*16+(g>>1)*8+r)*80 + (k16+(g&1)*8)*2);
            LDMX4(bh[2*p][0],bh[2*p][1],bh[2*p+1][0],bh[2*p+1][1], bd);
        }
        #pragma unroll
        for(int mt=0;mt<4;mt++)
            #pragma unroll
            for(int nt=0;nt<4;nt++)
                mma_bf16(acc[mt][nt], ah[mt][0],ah[mt][1],ah[mt][2],ah[mt][3],
                         bh[nt][0],bh[nt][1]);
        #pragma unroll
        for(int p=0;p<2;p++){
            unsigned bd = base + 30720u + (unsigned)((wn+p*16+(g>>1)*8+r)*80 + (k16+(g&1)*8)*2);
            LDMX4(bl[2*p][0],bl[2*p][1],bl[2*p+1][0],bl[2*p+1][1], bd);
        }
        #pragma unroll
        for(int mt=0;mt<4;mt++)
            #pragma unroll
            for(int nt=0;nt<4;nt++)
                mma_bf16(acc[mt][nt], ah[mt][0],ah[mt][1],ah[mt][2],ah[mt][3],
                         bl[nt][0],bl[nt][1]);
        #pragma unroll
        for(int mt=0;mt<4;mt++){
            unsigned ad = base + 10240u + (unsigned)((wm+mt*16+(g&1)*8+r)*80 + (k16+(g>>1)*8)*2);
            LDMX4(ah[mt][0],ah[mt][1],ah[mt][2],ah[mt][3], ad);
        }
        #pragma unroll
        for(int mt=0;mt<4;mt++)
            #pragma unroll
            for(int nt=0;nt<4;nt++)
                mma_bf16(acc[mt][nt], ah[mt][0],ah[mt][1],ah[mt][2],ah[mt][3],
                         bh[nt][0],bh[nt][1]);
    }
}

/* ------------------ transpose input + bf16 split --------------------------- */
__global__ void k_transpose_in(const float* __restrict__ x, float* __restrict__ xt,
                               __nv_bfloat16* __restrict__ xh, __nv_bfloat16* __restrict__ xl){
    int i = blockIdx.x*blockDim.x + threadIdx.x;
    if(i >= B_*N_) return;
    int b = i / N_, n = i % N_;
    #pragma unroll
    for(int c=0;c<3;c++){
        float v = x[((size_t)b*3+c)*N_ + n];
        xt[i*3+c] = v;
        __nv_bfloat16 h = __float2bfloat16(v);
        xh[i*16+c] = h;
        xl[i*16+c] = __float2bfloat16(v - __bfloat162float(h));
    }
    #pragma unroll
    for(int c=3;c<16;c++){ xh[i*16+c]=__float2bfloat16(0.f); xl[i*16+c]=__float2bfloat16(0.f); }
}

/* ---------------------- per-point squared norm ----------------------------- */
__global__ void k_xx(const float* __restrict__ xt, int C, int rs, float* __restrict__ xx){
    int i = blockIdx.x*blockDim.x + threadIdx.x;
    if(i >= B_*N_) return;
    const float* p = xt + (size_t)i*rs;
    float s = 0.f;
    for(int c=0;c<C;c++){ float v = p[c]; s += v*v; }
    xx[i] = s;
}

/* ---- pd keys, symmetric: upper-triangle tiles + mirrored smem transpose --- */
__global__ __launch_bounds__(256,2) void k_pd_mma(
        const __nv_bfloat16* __restrict__ Xh, const __nv_bfloat16* __restrict__ Xl,
        int rsIn, int Kpad, const float* __restrict__ xx, unsigned* __restrict__ pdk){
    extern __shared__ char smem[];
    unsigned sb = smem_u32(smem);
    int b = blockIdx.z;
    int ti = 0, rem = blockIdx.x;
    while(rem >= 16 - ti){ rem -= 16 - ti; ti++; }
    int tj = ti + rem;
    int n0 = ti*128, m0 = tj*128;
    bool diag = (ti == tj);
    int tid = threadIdx.x, wid = tid>>5, lane = tid&31;
    const __nv_bfloat16* Xhb = Xh + (size_t)b*N_*rsIn;
    const __nv_bfloat16* Xlb = Xl + (size_t)b*N_*rsIn;

    float acc[4][4][4];
    #pragma unroll
    for(int a=0;a<4;a++) for(int bq=0;bq<4;bq++) for(int cq=0;cq<4;cq++) acc[a][bq][cq]=0.f;

    int nch = (Kpad + KCH - 1)/KCH;
    ld_tile_bf16(smem, 0,     Xhb, n0, rsIn, 0, Kpad, tid);
    ld_tile_bf16(smem, 10240, Xlb, n0, rsIn, 0, Kpad, tid);
    ld_tile_bf16(smem, 20480, Xhb, m0, rsIn, 0, Kpad, tid);
    ld_tile_bf16(smem, 30720, Xlb, m0, rsIn, 0, Kpad, tid);
    __syncthreads();

    int wm = (wid>>2)*64, wn = (wid&3)*32;
    for(int c=0;c<nch;c++){
        int buf = c&1;
        if(c+1 < nch){
            int nb = (c+1)&1, k0 = (c+1)*KCH;
            ld_tile_bf16(smem, nb*STG+0,     Xhb, n0, rsIn, k0, Kpad, tid);
            ld_tile_bf16(smem, nb*STG+10240, Xlb, n0, rsIn, k0, Kpad, tid);
            ld_tile_bf16(smem, nb*STG+20480, Xhb, m0, rsIn, k0, Kpad, tid);
            ld_tile_bf16(smem, nb*STG+30720, Xlb, m0, rsIn, k0, Kpad, tid);
        }
        gemm_chunk(acc, sb + buf*STG, wm, wn, lane);
        __syncthreads();
    }

    const float* xxb = xx + b*N_;
    unsigned* sK = (unsigned*)smem;     /* 128x128 keys, pitch 129 words */
    int rr = lane>>2, cc = 2*(lane&3);
    #pragma unroll
    for(int mt=0;mt<4;mt++){
        int row = wm + mt*16 + rr;
        float xn0 = xxb[n0+row], xn8 = xxb[n0+row+8];
        #pragma unroll
        for(int nt=0;nt<4;nt++){
            int col = wn + nt*8 + cc;
            float xm0 = xxb[m0+col], xm1 = xxb[m0+col+1];
            uint2 u0, u1;
            u0.x = mkkey(2.f*acc[mt][nt][0] - xn0 - xm0);
            u0.y = mkkey(2.f*acc[mt][nt][1] - xn0 - xm1);
            u1.x = mkkey(2.f*acc[mt][nt][2] - xn8 - xm0);
            u1.y = mkkey(2.f*acc[mt][nt][3] - xn8 - xm1);
            if(diag){
                if(row   == col  ) u0.x = 0u;
                if(row   == col+1) u0.y = 0u;
                if(row+8 == col  ) u1.x = 0u;
                if(row+8 == col+1) u1.y = 0u;
            }
            *(uint2*)(pdk + ((size_t)b*N_ + n0+row  )*N_ + m0 + col) = u0;
            *(uint2*)(pdk + ((size_t)b*N_ + n0+row+8)*N_ + m0 + col) = u1;
            if(!diag){
                sK[ row   *129 + col  ] = u0.x;
                sK[ row   *129 + col+1] = u0.y;
                sK[(row+8)*129 + col  ] = u1.x;
                sK[(row+8)*129 + col+1] = u1.y;
            }
        }
    }
    if(!diag){
        __syncthreads();
        for(int i=0;i<16;i++){
            int r2 = wid + 8*i;
            size_t obase = ((size_t)b*N_ + m0 + r2)*N_ + n0;
            #pragma unroll
            for(int j=0;j<4;j++){
                int c2 = lane + 32*j;
                pdk[obase + c2] = sK[c2*129 + r2];
            }
        }
    }
}

/* ---- top-20: single 256-bin histogram + compaction + warp selection ------- */
__global__ void k_topk(const unsigned* __restrict__ pdk, int* __restrict__ idx){
    __shared__ unsigned hist[8][256];
    __shared__ unsigned sgs[256];
    __shared__ unsigned wtot[8], wabove[8];
    __shared__ int s_bin, s_above, s_outc, s_tiec;
    __shared__ unsigned tkey[2048];
    __shared__ unsigned short tidx[2048];

    int b = blockIdx.y, n = blockIdx.x;
    int tid = threadIdx.x, lane = tid & 31, wp = tid >> 5;
    const unsigned* row = pdk + ((size_t)b*N_ + n)*N_;

    unsigned key[8];
    #pragma unroll
    for(int j=0;j<8;j++) key[j] = row[tid + 256*j];   /* self already 0 */

    #pragma unroll
    for(int w=0;w<8;w++) hist[w][tid] = 0;
    if(tid==0){ s_outc = 0; s_tiec = 0; }
    __syncthreads();
    #pragma unroll
    for(int j=0;j<8;j++)
        if(key[j]) atomicAdd(&hist[wp][key[j]>>24], 1u);
    __syncthreads();

    unsigned c = 0;
    #pragma unroll
    for(int w=0;w<8;w++) c += hist[w][tid];
    unsigned s = c;
    #pragma unroll
    for(int off=1; off<32; off<<=1){
        unsigned o2 = __shfl_down_sync(0xffffffffu, s, off);
        if(lane + off < 32) s += o2;
    }
    if(lane==0) wtot[wp] = s;
    __syncthreads();
    if(tid==0){
        unsigned run=0;
        for(int w=7;w>=0;w--){ wabove[w]=run; run+=wtot[w]; }
    }
    __syncthreads();
    unsigned S = s + wabove[wp];
    sgs[tid] = S;
    __syncthreads();
    unsigned Snext = (tid<255) ? sgs[tid+1] : 0u;
    if(S >= (unsigned)KNN && Snext < (unsigned)KNN){
        s_bin = tid; s_above = (int)Snext;
    }
    __syncthreads();

    unsigned bin = (unsigned)s_bin;
    int rem = KNN - s_above;
    int* op = idx + ((b*N_)+n)*KNN;
    #pragma unroll
    for(int j=0;j<8;j++){
        unsigned kk = key[j];
        if(!kk) continue;
        unsigned hb = kk>>24;
        int m = tid + 256*j;
        if(hb > bin){
            int p = atomicAdd(&s_outc, 1);
            op[p] = m;
        } else if(hb == bin){
            int p = atomicAdd(&s_tiec, 1);
            tkey[p] = kk; tidx[p] = (unsigned short)m;
        }
    }
    __syncthreads();
    if(wp==0){
        int cg = s_outc, tc = s_tiec;
        for(int r=0;r<rem;r++){
            unsigned bk = 0; int bi = 0x7fffffff, bp = -1;
            for(int t=lane; t<tc; t+=32){
                unsigned kk = tkey[t];
                int ii = tidx[t];
                if(kk > bk || (kk == bk && ii < bi)){ bk = kk; bi = ii; bp = t; }
            }
            #pragma unroll
            for(int off=16; off>0; off>>=1){
                unsigned ok = __shfl_xor_sync(0xffffffffu, bk, off);
                int oi = __shfl_xor_sync(0xffffffffu, bi, off);
                int opp= __shfl_xor_sync(0xffffffffu, bp, off);
                if(ok > bk || (ok == bk && oi < bi)){ bk = ok; bi = oi; bp = opp; }
            }
            if(lane==0){ op[cg + r] = bi; tkey[bp] = 0u; }
            __syncwarp();
        }
    }
}

/* -------- conv1x1 (+BN+lrelu) via split bf16 mma.sync; emits bf16 twins ---- */
__global__ __launch_bounds__(256,2) void k_conv_mma(
        const float* __restrict__ W, int C2,
        const float* __restrict__ gg, const float* __restrict__ bb,
        const __nv_bfloat16* __restrict__ Hh, const __nv_bfloat16* __restrict__ Hl,
        int rsB, int Kpad, int O,
        float* __restrict__ yout, int rsOut, int oOff,
        __nv_bfloat16* __restrict__ couth, __nv_bfloat16* __restrict__ coutl, int wbf){
    extern __shared__ char smem[];
    unsigned sb = smem_u32(smem);
    int b = blockIdx.z, n0 = blockIdx.x*128, o0 = blockIdx.y*128;
    int tid = threadIdx.x, wid = tid>>5, lane = tid&31;
    const __nv_bfloat16* Hhb = Hh + (size_t)b*N_*rsB;
    const __nv_bfloat16* Hlb = Hl + (size_t)b*N_*rsB;

    float acc[4][4][4];
    #pragma unroll
    for(int a=0;a<4;a++) for(int bq=0;bq<4;bq++) for(int cq=0;cq<4;cq++) acc[a][bq][cq]=0.f;

    int nch = (Kpad + KCH - 1)/KCH;
    ld_tile_w  (smem, 0, 10240, W, o0, O, C2, 0, tid);
    ld_tile_bf16(smem, 20480, Hhb, n0, rsB, 0, Kpad, tid);
    ld_tile_bf16(smem, 30720, Hlb, n0, rsB, 0, Kpad, tid);
    __syncthreads();

    int wm = (wid>>2)*64, wn = (wid&3)*32;
    for(int c=0;c<nch;c++){
        int buf = c&1;
        if(c+1 < nch){
            int nb = (c+1)&1, k0 = (c+1)*KCH;
            ld_tile_w  (smem, nb*STG+0, nb*STG+10240, W, o0, O, C2, k0, tid);
            ld_tile_bf16(smem, nb*STG+20480, Hhb, n0, rsB, k0, Kpad, tid);
            ld_tile_bf16(smem, nb*STG+30720, Hlb, n0, rsB, k0, Kpad, tid);
        }
        gemm_chunk(acc, sb + buf*STG, wm, wn, lane);
        __syncthreads();
    }

    float* sC = (float*)smem;
    int rr = lane>>2, cc = 2*(lane&3);
    #pragma unroll
    for(int mt=0;mt<4;mt++){
        int row = wm + mt*16 + rr;
        #pragma unroll
        for(int nt=0;nt<4;nt++){
            int col = wn + nt*8 + cc;
            sC[ row   *129 + col  ] = acc[mt][nt][0];
            sC[ row   *129 + col+1] = acc[mt][nt][1];
            sC[(row+8)*129 + col  ] = acc[mt][nt][2];
            sC[(row+8)*129 + col+1] = acc[mt][nt][3];
        }
    }
    __syncthreads();

    int Olocal = O - o0; if(Olocal > 128) Olocal = 128;
    float scv[4], bsv[4];
    #pragma unroll
    for(int j=0;j<4;j++){
        int o = lane + 32*j;
        scv[j] = (o<Olocal) ? BNS*gg[o0+o] : 0.f;
        bsv[j] = (o<Olocal) ? bb[o0+o]     : 0.f;
    }
    for(int i=0;i<16;i++){
        int n = wid + 8*i;
        size_t rbase = (size_t)(b*N_ + n0 + n);
        #pragma unroll
        for(int j=0;j<4;j++){
            int o = lane + 32*j;
            if(o < Olocal){
                float y = lrelu(fmaf(sC[o*129+n], scv[j], bsv[j]));
                yout[rbase*rsOut + oOff + o0 + o] = y;
                if(wbf){
                    __nv_bfloat16 h = __float2bfloat16(y);
                    couth[rbase*512 + oOff + o0 + o] = h;
                    coutl[rbase*512 + oOff + o0 + o] = __float2bfloat16(y - __bfloat162float(h));
                }
            }
        }
    }
}

/* ---- attention aggregate: writes bf16 hi/lo h = [q, softmax.(key-q)] ------ */
__global__ void k_attn(const float* __restrict__ xt, int C, int rs,
                       const int* __restrict__ idx,
                       __nv_bfloat16* __restrict__ hH, __nv_bfloat16* __restrict__ hL,
                       int rsH){
    int b    = blockIdx.y;
    int warp = threadIdx.x >> 5, lane = threadIdx.x & 31;
    int n    = blockIdx.x*8 + warp;
    const float* Xb = xt + (size_t)b*N_*rs;
    float q[4];
    #pragma unroll
    for(int j=0;j<4;j++){
        int c = lane + 32*j;
        q[j] = (c<C) ? Xb[(size_t)n*rs + c] : 0.f;
    }
    const int* ip = idx + ((b*N_)+n)*KNN;
    int   nbr[KNN];
    float lg [KNN];
    for(int k=0;k<KNN;k++){
        int m = ip[k];
        nbr[k] = m;
        const float* kp = Xb + (size_t)m*rs;
        float p = 0.f;
        #pragma unroll
        for(int j=0;j<4;j++){
            int c = lane + 32*j;
            if(c<C) p += q[j]*kp[c];
        }
        #pragma unroll
        for(int o=16;o>0;o>>=1) p += __shfl_xor_sync(0xffffffffu,p,o);
        lg[k] = p;
    }
    float mx = -3e38f;
    #pragma unroll
    for(int k=0;k<KNN;k++) mx = fmaxf(mx, lg[k]);
    float Z = 0.f;
    #pragma unroll
    for(int k=0;k<KNN;k++){ lg[k] = expf(lg[k]-mx); Z += lg[k]; }
    float inv = 1.f/Z;
    size_t base = (size_t)(b*N_+n)*rsH;
    #pragma unroll
    for(int j=0;j<4;j++){
        int c = lane + 32*j;
        if(c<C){
            float f = 0.f;
            for(int k=0;k<KNN;k++) f += lg[k]*(Xb[(size_t)nbr[k]*rs + c] - q[j]);
            f *= inv;
            __nv_bfloat16 qh = __float2bfloat16(q[j]);
            hH[base + c]   = qh;
            hL[base + c]   = __float2bfloat16(q[j] - __bfloat162float(qh));
            __nv_bfloat16 fh = __float2bfloat16(f);
            hH[base + C + c] = fh;
            hL[base + C + c] = __float2bfloat16(f - __bfloat162float(fh));
        }
    }
    int extra = rsH - 2*C;
    if(extra > 0 && lane < extra){
        hH[base + 2*C + lane] = __float2bfloat16(0.f);
        hL[base + 2*C + lane] = __float2bfloat16(0.f);
    }
}

/* ------------ scores[b,n,h] = lrelu(sum_e x5[b,n,e] Watt[h,e]) ------------- */
__global__ void k_scores(const float* __restrict__ x5, const float* __restrict__ Watt,
                         float* __restrict__ sc){
    int gw   = (blockIdx.x*256 + threadIdx.x) >> 5;
    int lane = threadIdx.x & 31;
    if(gw >= B_*N_) return;
    const float* xp = x5 + (size_t)gw*1024;
    float a0=0,a1=0,a2=0,a3=0;
    for(int e=lane;e<1024;e+=32){
        float v = xp[e];
        a0 += v*Watt[e];
        a1 += v*Watt[1024+e];
        a2 += v*Watt[2048+e];
        a3 += v*Watt[3072+e];
    }
    #pragma unroll
    for(int o=16;o>0;o>>=1){
        a0 += __shfl_xor_sync(0xffffffffu,a0,o);
        a1 += __shfl_xor_sync(0xffffffffu,a1,o);
        a2 += __shfl_xor_sync(0xffffffffu,a2,o);
        a3 += __shfl_xor_sync(0xffffffffu,a3,o);
    }
    if(lane==0){
        sc[(size_t)gw*4+0] = lrelu(a0);
        sc[(size_t)gw*4+1] = lrelu(a1);
        sc[(size_t)gw*4+2] = lrelu(a2);
        sc[(size_t)gw*4+3] = lrelu(a3);
    }
}

/* ------------- att[b, h*1024+e] = sum_n x5[b,n,e] * sc[b,n,h] -------------- */
__global__ void k_attagg(const float* __restrict__ x5, const float* __restrict__ sc,
                         float* __restrict__ att){
    __shared__ float ssc[512*4];
    int b = blockIdx.y;
    int e = blockIdx.x*256 + threadIdx.x;
    float a0=0,a1=0,a2=0,a3=0;
    for(int n0=0;n0<N_;n0+=512){
        __syncthreads();
        for(int i=threadIdx.x;i<2048;i+=256)
            ssc[i] = sc[((size_t)b*N_+n0)*4 + i];
        __syncthreads();
        for(int nn=0;nn<512;nn++){
            float v = x5[((size_t)(b*N_+n0+nn))*1024 + e];
            a0 += v*ssc[nn*4+0];
            a1 += v*ssc[nn*4+1];
            a2 += v*ssc[nn*4+2];
            a3 += v*ssc[nn*4+3];
        }
    }
    att[b*4096 +    0 + e] = a0;
    att[b*4096 + 1024 + e] = a1;
    att[b*4096 + 2048 + e] = a2;
    att[b*4096 + 3072 + e] = a3;
}

/* ----------------------- LayerNorm(4096) + lrelu --------------------------- */
__global__ void k_ln(const float* __restrict__ att, const float* __restrict__ g,
                     const float* __restrict__ bt, float* __restrict__ out){
    __shared__ float red[256];
    int b = blockIdx.x, tid = threadIdx.x;
    const float* a = att + b*4096;
    float s=0.f;
    for(int i=tid;i<4096;i+=256) s += a[i];
    red[tid]=s; __syncthreads();
    for(int st=128;st>0;st>>=1){ if(tid<st) red[tid]+=red[tid+st]; __syncthreads(); }
    float mean = red[0]*(1.f/4096.f); __syncthreads();
    float v=0.f;
    for(int i=tid;i<4096;i+=256){ float d=a[i]-mean; v+=d*d; }
    red[tid]=v; __syncthreads();
    for(int st=128;st>0;st>>=1){ if(tid<st) red[tid]+=red[tid+st]; __syncthreads(); }
    float inv = 1.f/sqrtf(red[0]*(1.f/4096.f) + LNEPS);
    for(int i=tid;i<4096;i+=256){
        float y = (a[i]-mean)*inv*g[i] + bt[i];
        out[b*4096+i] = lrelu(y);
    }
}

/* ------------- warp-per-output fully-connected (+opt bnaff+lrelu) ---------- */
__global__ void k_fc(const float* __restrict__ A, const float* __restrict__ W,
                     const float* __restrict__ bias, const float* __restrict__ g,
                     const float* __restrict__ bt, float* __restrict__ out,
                     int K, int O, int mode){
    int gw   = (blockIdx.x*256 + threadIdx.x) >> 5;
    int lane = threadIdx.x & 31;
    if(gw >= B_*O) return;
    int b = gw / O, o = gw % O;
    const float* a = A + (size_t)b*K;
    const float* w = W + (size_t)o*K;
    float s=0.f;
    for(int k2=lane;k2<K;k2+=32) s += a[k2]*w[k2];
    #pragma unroll
    for(int off=16;off>0;off>>=1) s += __shfl_xor_sync(0xffffffffu,s,off);
    if(lane==0){
        s += bias[o];
        if(mode){ s = s*BNS*g[o] + bt[o]; s = lrelu(s); }
        out[(size_t)b*O+o] = s;
    }
}

/* ------------------------------- launcher ---------------------------------- */
extern "C" void kernel_launch(void* const* d_in, const int* in_sizes, int n_in,
                              void* d_out, int out_size){
    const float* x    = (const float*)d_in[0];
    const float* W1   = (const float*)d_in[1];
    const float* g1   = (const float*)d_in[2];
    const float* b1   = (const float*)d_in[3];
    const float* W2   = (const float*)d_in[4];
    const float* g2   = (const float*)d_in[5];
    const float* b2   = (const float*)d_in[6];
    const float* W3   = (const float*)d_in[7];
    const float* g3   = (const float*)d_in[8];
    const float* b3   = (const float*)d_in[9];
    const float* W4   = (const float*)d_in[10];
    const float* g4   = (const float*)d_in[11];
    const float* b4   = (const float*)d_in[12];
    const float* W5   = (const float*)d_in[13];
    const float* g5   = (const float*)d_in[14];
    const float* b5   = (const float*)d_in[15];
    const float* Watt = (const float*)d_in[16];
    const float* ln_g = (const float*)d_in[17];
    const float* ln_b = (const float*)d_in[18];
    const float* Wl1  = (const float*)d_in[19];
    const float* bl1  = (const float*)d_in[20];
    const float* g6   = (const float*)d_in[21];
    const float* b6   = (const float*)d_in[22];
    const float* Wl2  = (const float*)d_in[23];
    const float* bl2  = (const float*)d_in[24];
    const float* g7   = (const float*)d_in[25];
    const float* b7   = (const float*)d_in[26];
    const float* Wl3  = (const float*)d_in[27];
    const float* bl3  = (const float*)d_in[28];

    float *xt, *cat, *x5, *xx, *sc, *att, *attln, *y1, *y2;
    unsigned* pdk;
    int* idx;
    __nv_bfloat16 *xth, *xtl, *hh, *hl, *cath, *catl;
    cudaGetSymbolAddress((void**)&xt,   g_xt);
    cudaGetSymbolAddress((void**)&cat,  g_cat);
    cudaGetSymbolAddress((void**)&x5,   g_x5);
    cudaGetSymbolAddress((void**)&pdk,  g_pd);
    cudaGetSymbolAddress((void**)&xx,   g_xx);
    cudaGetSymbolAddress((void**)&idx,  g_idx);
    cudaGetSymbolAddress((void**)&sc,   g_sc);
    cudaGetSymbolAddress((void**)&att,  g_att);
    cudaGetSymbolAddress((void**)&attln,g_attln);
    cudaGetSymbolAddress((void**)&y1,   g_y1);
    cudaGetSymbolAddress((void**)&y2,   g_y2);
    cudaGetSymbolAddress((void**)&xth,  g_xth);
    cudaGetSymbolAddress((void**)&xtl,  g_xtl);
    cudaGetSymbolAddress((void**)&hh,   g_hh);
    cudaGetSymbolAddress((void**)&hl,   g_hl);
    cudaGetSymbolAddress((void**)&cath, g_cath);
    cudaGetSymbolAddress((void**)&catl, g_catl);

    cudaFuncSetAttribute(k_pd_mma,   cudaFuncAttributeMaxDynamicSharedMemorySize, SMEMB);
    cudaFuncSetAttribute(k_conv_mma, cudaFuncAttributeMaxDynamicSharedMemorySize, SMEMB);

    k_transpose_in<<<(B_*N_)/256, 256>>>(x, xt, xth, xtl);

    auto stage = [&](const float* XinF, int rsF,
                     const __nv_bfloat16* Xh, const __nv_bfloat16* Xl, int rsBf, int Kpad,
                     int C, const float* Wc, const float* gc, const float* bc,
                     int O, int rsH, int oOff){
        k_xx<<<(B_*N_)/256, 256>>>(XinF, C, rsF, xx);
        k_pd_mma<<<dim3(NTRI, 1, B_), 256, SMEMB>>>(Xh, Xl, rsBf, Kpad, xx, pdk);
        k_topk<<<dim3(N_, B_), 256>>>(pdk, idx);
        k_attn<<<dim3(N_/8, B_), 256>>>(XinF, C, rsF, idx, hh, hl, rsH);
        k_conv_mma<<<dim3(N_/128, (O+127)/128, B_), 256, SMEMB>>>(
            Wc, 2*C, gc, bc, hh, hl, rsH, rsH, O, cat, 512, oOff, cath, catl, 1);
    };

    stage(xt,        3,   xth,      xtl,      16,  16,  3,   W1, g1, b1,  64,  16,   0);
    stage(cat +   0, 512, cath+0,   catl+0,   512, 64,  64,  W2, g2, b2,  64,  128,  64);
    stage(cat +  64, 512, cath+64,  catl+64,  512, 64,  64,  W3, g3, b3, 128,  128, 128);
    stage(cat + 128, 512, cath+128, catl+128, 512, 128, 128, W4, g4, b4, 256,  256, 256);

    /* x5 = conv_bn(concat, W5) : C2=512, O=1024 */
    k_conv_mma<<<dim3(N_/128, 1024/128, B_), 256, SMEMB>>>(
        W5, 512, g5, b5, cath, catl, 512, 512, 1024, x5, 1024, 0,
        (__nv_bfloat16*)0, (__nv_bfloat16*)0, 0);

    k_scores<<<(B_*N_)/8, 256>>>(x5, Watt, sc);
    k_attagg<<<dim3(1024/256, B_), 256>>>(x5, sc, att);
    k_ln<<<B_, 256>>>(att, ln_g, ln_b, attln);

    k_fc<<<(B_*512)/8, 256>>>(attln, Wl1, bl1, g6, b6, y1, 4096, 512, 1);
    k_fc<<<(B_*256)/8, 256>>>(y1,    Wl2, bl2, g7, b7, y2,  512, 256, 1);
    k_fc<<<(B_*40 + 7)/8, 256>>>(y2, Wl3, bl3, (const float*)0, (const float*)0,
                                 (float*)d_out, 256, 40, 0);
}

// round 10
// speedup vs baseline: 1.1072x; 1.1072x over previous
#include <cuda_runtime.h>
#include <cuda_bf16.h>

#define NEG    0.2f
#define BNS    0.9999950000374997f   /* 1/sqrt(1+1e-5) */
#define LNEPS  1e-5f
#define B_     16
#define N_     2048
#define KNN    20

#define KCH   32                     /* K chunk */
#define STG   40960                  /* bytes per double-buffer stage */
#define SMEMB 81920
#define NTRI  136                    /* 16*17/2 upper-triangle tiles */

/* ------------- scratch (device globals; no runtime allocation) ------------- */
__device__ float g_xt  [B_*N_*3];
__device__ float g_cat [(size_t)B_*N_*512];
__device__ float g_x5  [(size_t)B_*N_*1024];
__device__ unsigned g_pd [(size_t)B_*N_*N_];      /* transformed order keys */
__device__ float g_xx  [B_*N_];
__device__ int   g_idx [B_*N_*KNN];
__device__ float g_sc  [B_*N_*4];
__device__ float g_att [B_*4096];
__device__ float g_attln[B_*4096];
__device__ float g_y1  [B_*512];
__device__ float g_y2  [B_*256];
__device__ __nv_bfloat16 g_xth[B_*N_*16];
__device__ __nv_bfloat16 g_xtl[B_*N_*16];
__device__ __nv_bfloat16 g_hh [(size_t)B_*N_*256];
__device__ __nv_bfloat16 g_hl [(size_t)B_*N_*256];
__device__ __nv_bfloat16 g_cath[(size_t)B_*N_*512];
__device__ __nv_bfloat16 g_catl[(size_t)B_*N_*512];
/* pre-split conv weights, padded to [Opad][rsW] */
__device__ __nv_bfloat16 g_w1h[128*32],    g_w1l[128*32];
__device__ __nv_bfloat16 g_w2h[128*128],   g_w2l[128*128];
__device__ __nv_bfloat16 g_w3h[128*128],   g_w3l[128*128];
__device__ __nv_bfloat16 g_w4h[256*256],   g_w4l[256*256];
__device__ __nv_bfloat16 g_w5h[1024*512],  g_w5l[1024*512];

__device__ __forceinline__ float lrelu(float v){ return v > 0.f ? v : NEG*v; }
__device__ __forceinline__ unsigned mkkey(float v){
    unsigned u = __float_as_uint(v);
    return (u & 0x80000000u) ? ~u : (u | 0x80000000u);
}

__device__ __forceinline__ unsigned smem_u32(const void* p){
    unsigned a;
    asm("{ .reg .u64 t; cvta.to.shared.u64 t, %1; cvt.u32.u64 %0, t; }":"=r"(a):"l"(p));
    return a;
}
#define LDMX4(r0,r1,r2,r3,a) \
    asm volatile("ldmatrix.sync.aligned.m8n8.x4.shared.b16 {%0,%1,%2,%3}, [%4];" \
        : "=r"(r0),"=r"(r1),"=r"(r2),"=r"(r3) : "r"(a))

__device__ __forceinline__ void mma_bf16(float* c, unsigned a0,unsigned a1,unsigned a2,unsigned a3,
                                         unsigned b0,unsigned b1){
    asm volatile("mma.sync.aligned.m16n8k16.row.col.f32.bf16.bf16.f32 "
        "{%0,%1,%2,%3},{%4,%5,%6,%7},{%8,%9},{%0,%1,%2,%3};"
        : "+f"(c[0]),"+f"(c[1]),"+f"(c[2]),"+f"(c[3])
        : "r"(a0),"r"(a1),"r"(a2),"r"(a3),"r"(b0),"r"(b1));
}

/* bf16 tile loader: 128 rows x 32 cols into smem, row pitch 80B */
__device__ __forceinline__ void ld_tile_bf16(char* sm, int off,
        const __nv_bfloat16* __restrict__ src, int row0, int rsIn, int k0, int Kpad, int tid){
    for(int i=tid;i<512;i+=256){
        int r=i>>2, q=i&3, k=k0+q*8;
        uint4 v = make_uint4(0,0,0,0);
        if(k < Kpad) v = *(const uint4*)(src + (size_t)(row0+r)*rsIn + k);
        *(uint4*)(sm + off + r*80 + q*16) = v;
    }
}

/* one K-chunk (32) of split-precision mma */
__device__ __forceinline__ void gemm_chunk(float (&acc)[4][4][4], unsigned base,
                                           int wm, int wn, int lane){
    int g = lane>>3, r = lane&7;
    #pragma unroll
    for(int h=0;h<2;h++){
        int k16 = h*16;
        unsigned ah[4][4], bh[4][2], bl[4][2];
        #pragma unroll
        for(int mt=0;mt<4;mt++){
            unsigned ad = base + (unsigned)((wm+mt*16+(g&1)*8+r)*80 + (k16+(g>>1)*8)*2);
            LDMX4(ah[mt][0],ah[mt][1],ah[mt][2],ah[mt][3], ad);
        }
        #pragma unroll
        for(int p=0;p<2;p++){
            unsigned bd = base + 20480u + (unsigned)((wn+p*16+(g>>1)*8+r)*80 + (k16+(g&1)*8)*2);
            LDMX4(bh[2*p][0],bh[2*p][1],bh[2*p+1][0],bh[2*p+1][1], bd);
        }
        #pragma unroll
        for(int mt=0;mt<4;mt++)
            #pragma unroll
            for(int nt=0;nt<4;nt++)
                mma_bf16(acc[mt][nt], ah[mt][0],ah[mt][1],ah[mt][2],ah[mt][3],
                         bh[nt][0],bh[nt][1]);
        #pragma unroll
        for(int p=0;p<2;p++){
            unsigned bd = base + 30720u + (unsigned)((wn+p*16+(g>>1)*8+r)*80 + (k16+(g&1)*8)*2);
            LDMX4(bl[2*p][0],bl[2*p][1],bl[2*p+1][0],bl[2*p+1][1], bd);
        }
        #pragma unroll
        for(int mt=0;mt<4;mt++)
            #pragma unroll
            for(int nt=0;nt<4;nt++)
                mma_bf16(acc[mt][nt], ah[mt][0],ah[mt][1],ah[mt][2],ah[mt][3],
                         bl[nt][0],bl[nt][1]);
        #pragma unroll
        for(int mt=0;mt<4;mt++){
            unsigned ad = base + 10240u + (unsigned)((wm+mt*16+(g&1)*8+r)*80 + (k16+(g>>1)*8)*2);
            LDMX4(ah[mt][0],ah[mt][1],ah[mt][2],ah[mt][3], ad);
        }
        #pragma unroll
        for(int mt=0;mt<4;mt++)
            #pragma unroll
            for(int nt=0;nt<4;nt++)
                mma_bf16(acc[mt][nt], ah[mt][0],ah[mt][1],ah[mt][2],ah[mt][3],
                         bh[nt][0],bh[nt][1]);
    }
}

/* ------------- weight pre-split: fp32 [O][C2] -> padded bf16 h/l ----------- */
__global__ void k_wsplit(const float* __restrict__ W, int O, int C2,
                         int Opad, int rsW,
                         __nv_bfloat16* __restrict__ Wh, __nv_bfloat16* __restrict__ Wl){
    int i = blockIdx.x*256 + threadIdx.x;
    if(i >= Opad*rsW) return;
    int o = i / rsW, k = i % rsW;
    float v = (o < O && k < C2) ? W[(size_t)o*C2 + k] : 0.f;
    __nv_bfloat16 h = __float2bfloat16(v);
    Wh[i] = h;
    Wl[i] = __float2bfloat16(v - __bfloat162float(h));
}

/* ------------------ transpose input + bf16 split --------------------------- */
__global__ void k_transpose_in(const float* __restrict__ x, float* __restrict__ xt,
                               __nv_bfloat16* __restrict__ xh, __nv_bfloat16* __restrict__ xl){
    int i = blockIdx.x*blockDim.x + threadIdx.x;
    if(i >= B_*N_) return;
    int b = i / N_, n = i % N_;
    #pragma unroll
    for(int c=0;c<3;c++){
        float v = x[((size_t)b*3+c)*N_ + n];
        xt[i*3+c] = v;
        __nv_bfloat16 h = __float2bfloat16(v);
        xh[i*16+c] = h;
        xl[i*16+c] = __float2bfloat16(v - __bfloat162float(h));
    }
    #pragma unroll
    for(int c=3;c<16;c++){ xh[i*16+c]=__float2bfloat16(0.f); xl[i*16+c]=__float2bfloat16(0.f); }
}

/* ---------------------- per-point squared norm ----------------------------- */
__global__ void k_xx(const float* __restrict__ xt, int C, int rs, float* __restrict__ xx){
    int i = blockIdx.x*blockDim.x + threadIdx.x;
    if(i >= B_*N_) return;
    const float* p = xt + (size_t)i*rs;
    float s = 0.f;
    for(int c=0;c<C;c++){ float v = p[c]; s += v*v; }
    xx[i] = s;
}

/* ---- pd keys, symmetric: upper-triangle tiles + mirrored smem transpose --- */
__global__ __launch_bounds__(256,2) void k_pd_mma(
        const __nv_bfloat16* __restrict__ Xh, const __nv_bfloat16* __restrict__ Xl,
        int rsIn, int Kpad, const float* __restrict__ xx, unsigned* __restrict__ pdk){
    extern __shared__ char smem[];
    unsigned sb = smem_u32(smem);
    int b = blockIdx.z;
    int ti = 0, rem = blockIdx.x;
    while(rem >= 16 - ti){ rem -= 16 - ti; ti++; }
    int tj = ti + rem;
    int n0 = ti*128, m0 = tj*128;
    bool diag = (ti == tj);
    int tid = threadIdx.x, wid = tid>>5, lane = tid&31;
    const __nv_bfloat16* Xhb = Xh + (size_t)b*N_*rsIn;
    const __nv_bfloat16* Xlb = Xl + (size_t)b*N_*rsIn;

    float acc[4][4][4];
    #pragma unroll
    for(int a=0;a<4;a++) for(int bq=0;bq<4;bq++) for(int cq=0;cq<4;cq++) acc[a][bq][cq]=0.f;

    int nch = (Kpad + KCH - 1)/KCH;
    ld_tile_bf16(smem, 0,     Xhb, n0, rsIn, 0, Kpad, tid);
    ld_tile_bf16(smem, 10240, Xlb, n0, rsIn, 0, Kpad, tid);
    ld_tile_bf16(smem, 20480, Xhb, m0, rsIn, 0, Kpad, tid);
    ld_tile_bf16(smem, 30720, Xlb, m0, rsIn, 0, Kpad, tid);
    __syncthreads();

    int wm = (wid>>2)*64, wn = (wid&3)*32;
    for(int c=0;c<nch;c++){
        int buf = c&1;
        if(c+1 < nch){
            int nb = (c+1)&1, k0 = (c+1)*KCH;
            ld_tile_bf16(smem, nb*STG+0,     Xhb, n0, rsIn, k0, Kpad, tid);
            ld_tile_bf16(smem, nb*STG+10240, Xlb, n0, rsIn, k0, Kpad, tid);
            ld_tile_bf16(smem, nb*STG+20480, Xhb, m0, rsIn, k0, Kpad, tid);
            ld_tile_bf16(smem, nb*STG+30720, Xlb, m0, rsIn, k0, Kpad, tid);
        }
        gemm_chunk(acc, sb + buf*STG, wm, wn, lane);
        __syncthreads();
    }

    const float* xxb = xx + b*N_;
    unsigned* sK = (unsigned*)smem;     /* 128x128 keys, pitch 129 words */
    int rr = lane>>2, cc = 2*(lane&3);
    #pragma unroll
    for(int mt=0;mt<4;mt++){
        int row = wm + mt*16 + rr;
        float xn0 = xxb[n0+row], xn8 = xxb[n0+row+8];
        #pragma unroll
        for(int nt=0;nt<4;nt++){
            int col = wn + nt*8 + cc;
            float xm0 = xxb[m0+col], xm1 = xxb[m0+col+1];
            uint2 u0, u1;
            u0.x = mkkey(2.f*acc[mt][nt][0] - xn0 - xm0);
            u0.y = mkkey(2.f*acc[mt][nt][1] - xn0 - xm1);
            u1.x = mkkey(2.f*acc[mt][nt][2] - xn8 - xm0);
            u1.y = mkkey(2.f*acc[mt][nt][3] - xn8 - xm1);
            if(diag){
                if(row   == col  ) u0.x = 0u;
                if(row   == col+1) u0.y = 0u;
                if(row+8 == col  ) u1.x = 0u;
                if(row+8 == col+1) u1.y = 0u;
            }
            *(uint2*)(pdk + ((size_t)b*N_ + n0+row  )*N_ + m0 + col) = u0;
            *(uint2*)(pdk + ((size_t)b*N_ + n0+row+8)*N_ + m0 + col) = u1;
            if(!diag){
                sK[ row   *129 + col  ] = u0.x;
                sK[ row   *129 + col+1] = u0.y;
                sK[(row+8)*129 + col  ] = u1.x;
                sK[(row+8)*129 + col+1] = u1.y;
            }
        }
    }
    if(!diag){
        __syncthreads();
        for(int i=0;i<16;i++){
            int r2 = wid + 8*i;
            size_t obase = ((size_t)b*N_ + m0 + r2)*N_ + n0;
            #pragma unroll
            for(int j=0;j<4;j++){
                int c2 = lane + 32*j;
                pdk[obase + c2] = sK[c2*129 + r2];
            }
        }
    }
}

/* ------- top-20 per row, 4-level 8-bit radix select on precomputed keys ---- */
__global__ void k_topk(const unsigned* __restrict__ pdk, int* __restrict__ idx){
    __shared__ unsigned hist[8][256];
    __shared__ unsigned sgs[256];
    __shared__ unsigned wtot[8], wabove[8];
    __shared__ int s_bin, s_above, s_outc, s_tiec;
    __shared__ int ties[2048];

    int b = blockIdx.y, n = blockIdx.x;
    int tid = threadIdx.x, lane = tid & 31, wp = tid >> 5;
    const unsigned* row = pdk + ((size_t)b*N_ + n)*N_;

    unsigned key[8];
    #pragma unroll
    for(int j=0;j<8;j++) key[j] = row[tid + 256*j];   /* self already 0 */

    unsigned prefix = 0, pmask = 0;
    int kneed = KNN;
    for(int level=0; level<4; level++){
        int shift = 24 - 8*level;
        #pragma unroll
        for(int w=0;w<8;w++) hist[w][tid] = 0;
        __syncthreads();
        #pragma unroll
        for(int j=0;j<8;j++){
            unsigned kk = key[j];
            if((kk & pmask) == prefix)
                atomicAdd(&hist[wp][(kk>>shift)&255u], 1u);
        }
        __syncthreads();
        unsigned c = 0;
        #pragma unroll
        for(int w=0;w<8;w++) c += hist[w][tid];
        unsigned s = c;
        #pragma unroll
        for(int off=1; off<32; off<<=1){
            unsigned o2 = __shfl_down_sync(0xffffffffu, s, off);
            if(lane + off < 32) s += o2;
        }
        if(lane==0) wtot[wp] = s;
        __syncthreads();
        if(tid==0){
            unsigned run=0;
            for(int w=7;w>=0;w--){ wabove[w]=run; run+=wtot[w]; }
        }
        __syncthreads();
        unsigned S = s + wabove[wp];
        sgs[tid] = S;
        __syncthreads();
        unsigned Snext = (tid<255) ? sgs[tid+1] : 0u;
        if(S >= (unsigned)kneed && Snext < (unsigned)kneed){
            s_bin = tid; s_above = (int)Snext;
        }
        __syncthreads();
        prefix |= ((unsigned)s_bin) << shift;
        pmask  |= 0xFFu << shift;
        kneed  -= s_above;
        __syncthreads();
    }

    unsigned T = prefix;
    int rem = kneed;                      /* # of ==T to take, >=1 */
    int* op = idx + ((b*N_)+n)*KNN;
    if(tid==0){ s_outc = 0; s_tiec = 0; }
    __syncthreads();
    #pragma unroll
    for(int j=0;j<8;j++){
        unsigned kk = key[j]; int m = tid + 256*j;
        if(kk > T){
            int p = atomicAdd(&s_outc, 1);
            op[p] = m;
        } else if(kk == T){
            int p = atomicAdd(&s_tiec, 1);
            ties[p] = m;
        }
    }
    __syncthreads();
    int cg = s_outc;
    if(wp==0){
        int tc = s_tiec;
        for(int r=0;r<rem;r++){
            int best = 0x7fffffff, bpos = -1;
            for(int t2=lane; t2<tc; t2+=32){
                int v = ties[t2];
                if(v < best){ best = v; bpos = t2; }
            }
            #pragma unroll
            for(int off=16; off>0; off>>=1){
                int ov = __shfl_xor_sync(0xffffffffu, best, off);
                int opo= __shfl_xor_sync(0xffffffffu, bpos, off);
                if(ov < best){ best = ov; bpos = opo; }
            }
            if(lane==0){ op[cg + r] = best; ties[bpos] = 0x7fffffff; }
            __syncwarp();
        }
    }
}

/* -------- conv1x1 (+BN+lrelu), pre-split bf16 weights; emits bf16 twins ---- */
__global__ __launch_bounds__(256,2) void k_conv_mma(
        const __nv_bfloat16* __restrict__ Wh, const __nv_bfloat16* __restrict__ Wl, int rsW,
        const float* __restrict__ gg, const float* __restrict__ bb,
        const __nv_bfloat16* __restrict__ Hh, const __nv_bfloat16* __restrict__ Hl,
        int rsB, int Kpad, int O,
        float* __restrict__ yout, int rsOut, int oOff,
        __nv_bfloat16* __restrict__ couth, __nv_bfloat16* __restrict__ coutl, int wbf){
    extern __shared__ char smem[];
    unsigned sb = smem_u32(smem);
    int b = blockIdx.z, n0 = blockIdx.x*128, o0 = blockIdx.y*128;
    int tid = threadIdx.x, wid = tid>>5, lane = tid&31;
    const __nv_bfloat16* Hhb = Hh + (size_t)b*N_*rsB;
    const __nv_bfloat16* Hlb = Hl + (size_t)b*N_*rsB;

    float acc[4][4][4];
    #pragma unroll
    for(int a=0;a<4;a++) for(int bq=0;bq<4;bq++) for(int cq=0;cq<4;cq++) acc[a][bq][cq]=0.f;

    int nch = (Kpad + KCH - 1)/KCH;
    ld_tile_bf16(smem, 0,     Wh,  o0, rsW, 0, Kpad, tid);
    ld_tile_bf16(smem, 10240, Wl,  o0, rsW, 0, Kpad, tid);
    ld_tile_bf16(smem, 20480, Hhb, n0, rsB, 0, Kpad, tid);
    ld_tile_bf16(smem, 30720, Hlb, n0, rsB, 0, Kpad, tid);
    __syncthreads();

    int wm = (wid>>2)*64, wn = (wid&3)*32;
    for(int c=0;c<nch;c++){
        int buf = c&1;
        if(c+1 < nch){
            int nb = (c+1)&1, k0 = (c+1)*KCH;
            ld_tile_bf16(smem, nb*STG+0,     Wh,  o0, rsW, k0, Kpad, tid);
            ld_tile_bf16(smem, nb*STG+10240, Wl,  o0, rsW, k0, Kpad, tid);
            ld_tile_bf16(smem, nb*STG+20480, Hhb, n0, rsB, k0, Kpad, tid);
            ld_tile_bf16(smem, nb*STG+30720, Hlb, n0, rsB, k0, Kpad, tid);
        }
        gemm_chunk(acc, sb + buf*STG, wm, wn, lane);
        __syncthreads();
    }

    float* sC = (float*)smem;
    int rr = lane>>2, cc = 2*(lane&3);
    #pragma unroll
    for(int mt=0;mt<4;mt++){
        int row = wm + mt*16 + rr;
        #pragma unroll
        for(int nt=0;nt<4;nt++){
            int col = wn + nt*8 + cc;
            sC[ row   *129 + col  ] = acc[mt][nt][0];
            sC[ row   *129 + col+1] = acc[mt][nt][1];
            sC[(row+8)*129 + col  ] = acc[mt][nt][2];
            sC[(row+8)*129 + col+1] = acc[mt][nt][3];
        }
    }
    __syncthreads();

    int Olocal = O - o0; if(Olocal > 128) Olocal = 128;
    float scv[4], bsv[4];
    #pragma unroll
    for(int j=0;j<4;j++){
        int o = lane + 32*j;
        scv[j] = (o<Olocal) ? BNS*gg[o0+o] : 0.f;
        bsv[j] = (o<Olocal) ? bb[o0+o]     : 0.f;
    }
    for(int i=0;i<16;i++){
        int n = wid + 8*i;
        size_t rbase = (size_t)(b*N_ + n0 + n);
        #pragma unroll
        for(int j=0;j<4;j++){
            int o = lane + 32*j;
            if(o < Olocal){
                float y = lrelu(fmaf(sC[o*129+n], scv[j], bsv[j]));
                yout[rbase*rsOut + oOff + o0 + o] = y;
                if(wbf){
                    __nv_bfloat16 h = __float2bfloat16(y);
                    couth[rbase*512 + oOff + o0 + o] = h;
                    coutl[rbase*512 + oOff + o0 + o] = __float2bfloat16(y - __bfloat162float(h));
                }
            }
        }
    }
}

/* ---- attention aggregate: writes bf16 hi/lo h = [q, softmax.(key-q)] ------ */
__global__ void k_attn(const float* __restrict__ xt, int C, int rs,
                       const int* __restrict__ idx,
                       __nv_bfloat16* __restrict__ hH, __nv_bfloat16* __restrict__ hL,
                       int rsH){
    int b    = blockIdx.y;
    int warp = threadIdx.x >> 5, lane = threadIdx.x & 31;
    int n    = blockIdx.x*8 + warp;
    const float* Xb = xt + (size_t)b*N_*rs;
    float q[4];
    #pragma unroll
    for(int j=0;j<4;j++){
        int c = lane + 32*j;
        q[j] = (c<C) ? Xb[(size_t)n*rs + c] : 0.f;
    }
    const int* ip = idx + ((b*N_)+n)*KNN;
    int   nbr[KNN];
    float lg [KNN];
    for(int k=0;k<KNN;k++){
        int m = ip[k];
        nbr[k] = m;
        const float* kp = Xb + (size_t)m*rs;
        float p = 0.f;
        #pragma unroll
        for(int j=0;j<4;j++){
            int c = lane + 32*j;
            if(c<C) p += q[j]*kp[c];
        }
        #pragma unroll
        for(int o=16;o>0;o>>=1) p += __shfl_xor_sync(0xffffffffu,p,o);
        lg[k] = p;
    }
    float mx = -3e38f;
    #pragma unroll
    for(int k=0;k<KNN;k++) mx = fmaxf(mx, lg[k]);
    float Z = 0.f;
    #pragma unroll
    for(int k=0;k<KNN;k++){ lg[k] = expf(lg[k]-mx); Z += lg[k]; }
    float inv = 1.f/Z;
    size_t base = (size_t)(b*N_+n)*rsH;
    #pragma unroll
    for(int j=0;j<4;j++){
        int c = lane + 32*j;
        if(c<C){
            float f = 0.f;
            for(int k=0;k<KNN;k++) f += lg[k]*(Xb[(size_t)nbr[k]*rs + c] - q[j]);
            f *= inv;
            __nv_bfloat16 qh = __float2bfloat16(q[j]);
            hH[base + c]   = qh;
            hL[base + c]   = __float2bfloat16(q[j] - __bfloat162float(qh));
            __nv_bfloat16 fh = __float2bfloat16(f);
            hH[base + C + c] = fh;
            hL[base + C + c] = __float2bfloat16(f - __bfloat162float(fh));
        }
    }
    int extra = rsH - 2*C;
    if(extra > 0 && lane < extra){
        hH[base + 2*C + lane] = __float2bfloat16(0.f);
        hL[base + 2*C + lane] = __float2bfloat16(0.f);
    }
}

/* ------------ scores[b,n,h] = lrelu(sum_e x5[b,n,e] Watt[h,e]) ------------- */
__global__ void k_scores(const float* __restrict__ x5, const float* __restrict__ Watt,
                         float* __restrict__ sc){
    int gw   = (blockIdx.x*256 + threadIdx.x) >> 5;
    int lane = threadIdx.x & 31;
    if(gw >= B_*N_) return;
    const float* xp = x5 + (size_t)gw*1024;
    float a0=0,a1=0,a2=0,a3=0;
    for(int e=lane;e<1024;e+=32){
        float v = xp[e];
        a0 += v*Watt[e];
        a1 += v*Watt[1024+e];
        a2 += v*Watt[2048+e];
        a3 += v*Watt[3072+e];
    }
    #pragma unroll
    for(int o=16;o>0;o>>=1){
        a0 += __shfl_xor_sync(0xffffffffu,a0,o);
        a1 += __shfl_xor_sync(0xffffffffu,a1,o);
        a2 += __shfl_xor_sync(0xffffffffu,a2,o);
        a3 += __shfl_xor_sync(0xffffffffu,a3,o);
    }
    if(lane==0){
        sc[(size_t)gw*4+0] = lrelu(a0);
        sc[(size_t)gw*4+1] = lrelu(a1);
        sc[(size_t)gw*4+2] = lrelu(a2);
        sc[(size_t)gw*4+3] = lrelu(a3);
    }
}

/* ------------- att[b, h*1024+e] = sum_n x5[b,n,e] * sc[b,n,h] -------------- */
__global__ void k_attagg(const float* __restrict__ x5, const float* __restrict__ sc,
                         float* __restrict__ att){
    __shared__ float ssc[512*4];
    int b = blockIdx.y;
    int e = blockIdx.x*256 + threadIdx.x;
    float a0=0,a1=0,a2=0,a3=0;
    for(int n0=0;n0<N_;n0+=512){
        __syncthreads();
        for(int i=threadIdx.x;i<2048;i+=256)
            ssc[i] = sc[((size_t)b*N_+n0)*4 + i];
        __syncthreads();
        for(int nn=0;nn<512;nn++){
            float v = x5[((size_t)(b*N_+n0+nn))*1024 + e];
            a0 += v*ssc[nn*4+0];
            a1 += v*ssc[nn*4+1];
            a2 += v*ssc[nn*4+2];
            a3 += v*ssc[nn*4+3];
        }
    }
    att[b*4096 +    0 + e] = a0;
    att[b*4096 + 1024 + e] = a1;
    att[b*4096 + 2048 + e] = a2;
    att[b*4096 + 3072 + e] = a3;
}

/* ----------------------- LayerNorm(4096) + lrelu --------------------------- */
__global__ void k_ln(const float* __restrict__ att, const float* __restrict__ g,
                     const float* __restrict__ bt, float* __restrict__ out){
    __shared__ float red[256];
    int b = blockIdx.x, tid = threadIdx.x;
    const float* a = att + b*4096;
    float s=0.f;
    for(int i=tid;i<4096;i+=256) s += a[i];
    red[tid]=s; __syncthreads();
    for(int st=128;st>0;st>>=1){ if(tid<st) red[tid]+=red[tid+st]; __syncthreads(); }
    float mean = red[0]*(1.f/4096.f); __syncthreads();
    float v=0.f;
    for(int i=tid;i<4096;i+=256){ float d=a[i]-mean; v+=d*d; }
    red[tid]=v; __syncthreads();
    for(int st=128;st>0;st>>=1){ if(tid<st) red[tid]+=red[tid+st]; __syncthreads(); }
    float inv = 1.f/sqrtf(red[0]*(1.f/4096.f) + LNEPS);
    for(int i=tid;i<4096;i+=256){
        float y = (a[i]-mean)*inv*g[i] + bt[i];
        out[b*4096+i] = lrelu(y);
    }
}

/* ------------- warp-per-output fully-connected (+opt bnaff+lrelu) ---------- */
__global__ void k_fc(const float* __restrict__ A, const float* __restrict__ W,
                     const float* __restrict__ bias, const float* __restrict__ g,
                     const float* __restrict__ bt, float* __restrict__ out,
                     int K, int O, int mode){
    int gw   = (blockIdx.x*256 + threadIdx.x) >> 5;
    int lane = threadIdx.x & 31;
    if(gw >= B_*O) return;
    int b = gw / O, o = gw % O;
    const float* a = A + (size_t)b*K;
    const float* w = W + (size_t)o*K;
    float s=0.f;
    for(int k2=lane;k2<K;k2+=32) s += a[k2]*w[k2];
    #pragma unroll
    for(int off=16;off>0;off>>=1) s += __shfl_xor_sync(0xffffffffu,s,off);
    if(lane==0){
        s += bias[o];
        if(mode){ s = s*BNS*g[o] + bt[o]; s = lrelu(s); }
        out[(size_t)b*O+o] = s;
    }
}

/* ------------------------------- launcher ---------------------------------- */
extern "C" void kernel_launch(void* const* d_in, const int* in_sizes, int n_in,
                              void* d_out, int out_size){
    const float* x    = (const float*)d_in[0];
    const float* W1   = (const float*)d_in[1];
    const float* g1   = (const float*)d_in[2];
    const float* b1   = (const float*)d_in[3];
    const float* W2   = (const float*)d_in[4];
    const float* g2   = (const float*)d_in[5];
    const float* b2   = (const float*)d_in[6];
    const float* W3   = (const float*)d_in[7];
    const float* g3   = (const float*)d_in[8];
    const float* b3   = (const float*)d_in[9];
    const float* W4   = (const float*)d_in[10];
    const float* g4   = (const float*)d_in[11];
    const float* b4   = (const float*)d_in[12];
    const float* W5   = (const float*)d_in[13];
    const float* g5   = (const float*)d_in[14];
    const float* b5   = (const float*)d_in[15];
    const float* Watt = (const float*)d_in[16];
    const float* ln_g = (const float*)d_in[17];
    const float* ln_b = (const float*)d_in[18];
    const float* Wl1  = (const float*)d_in[19];
    const float* bl1  = (const float*)d_in[20];
    const float* g6   = (const float*)d_in[21];
    const float* b6   = (const float*)d_in[22];
    const float* Wl2  = (const float*)d_in[23];
    const float* bl2  = (const float*)d_in[24];
    const float* g7   = (const float*)d_in[25];
    const float* b7   = (const float*)d_in[26];
    const float* Wl3  = (const float*)d_in[27];
    const float* bl3  = (const float*)d_in[28];

    float *xt, *cat, *x5, *xx, *sc, *att, *attln, *y1, *y2;
    unsigned* pdk;
    int* idx;
    __nv_bfloat16 *xth, *xtl, *hh, *hl, *cath, *catl;
    __nv_bfloat16 *w1h,*w1l,*w2h,*w2l,*w3h,*w3l,*w4h,*w4l,*w5h,*w5l;
    cudaGetSymbolAddress((void**)&xt,   g_xt);
    cudaGetSymbolAddress((void**)&cat,  g_cat);
    cudaGetSymbolAddress((void**)&x5,   g_x5);
    cudaGetSymbolAddress((void**)&pdk,  g_pd);
    cudaGetSymbolAddress((void**)&xx,   g_xx);
    cudaGetSymbolAddress((void**)&idx,  g_idx);
    cudaGetSymbolAddress((void**)&sc,   g_sc);
    cudaGetSymbolAddress((void**)&att,  g_att);
    cudaGetSymbolAddress((void**)&attln,g_attln);
    cudaGetSymbolAddress((void**)&y1,   g_y1);
    cudaGetSymbolAddress((void**)&y2,   g_y2);
    cudaGetSymbolAddress((void**)&xth,  g_xth);
    cudaGetSymbolAddress((void**)&xtl,  g_xtl);
    cudaGetSymbolAddress((void**)&hh,   g_hh);
    cudaGetSymbolAddress((void**)&hl,   g_hl);
    cudaGetSymbolAddress((void**)&cath, g_cath);
    cudaGetSymbolAddress((void**)&catl, g_catl);
    cudaGetSymbolAddress((void**)&w1h,  g_w1h);
    cudaGetSymbolAddress((void**)&w1l,  g_w1l);
    cudaGetSymbolAddress((void**)&w2h,  g_w2h);
    cudaGetSymbolAddress((void**)&w2l,  g_w2l);
    cudaGetSymbolAddress((void**)&w3h,  g_w3h);
    cudaGetSymbolAddress((void**)&w3l,  g_w3l);
    cudaGetSymbolAddress((void**)&w4h,  g_w4h);
    cudaGetSymbolAddress((void**)&w4l,  g_w4l);
    cudaGetSymbolAddress((void**)&w5h,  g_w5h);
    cudaGetSymbolAddress((void**)&w5l,  g_w5l);

    cudaFuncSetAttribute(k_pd_mma,   cudaFuncAttributeMaxDynamicSharedMemorySize, SMEMB);
    cudaFuncSetAttribute(k_conv_mma, cudaFuncAttributeMaxDynamicSharedMemorySize, SMEMB);

    /* weight pre-split (padded Opad x rsW) */
    k_wsplit<<<(128*32  + 255)/256, 256>>>(W1,   64,   6, 128,  32, w1h, w1l);
    k_wsplit<<<(128*128 + 255)/256, 256>>>(W2,   64, 128, 128, 128, w2h, w2l);
    k_wsplit<<<(128*128 + 255)/256, 256>>>(W3,  128, 128, 128, 128, w3h, w3l);
    k_wsplit<<<(256*256 + 255)/256, 256>>>(W4,  256, 256, 256, 256, w4h, w4l);
    k_wsplit<<<(1024*512+ 255)/256, 256>>>(W5, 1024, 512,1024, 512, w5h, w5l);

    k_transpose_in<<<(B_*N_)/256, 256>>>(x, xt, xth, xtl);

    auto stage = [&](const float* XinF, int rsF,
                     const __nv_bfloat16* Xh, const __nv_bfloat16* Xl, int rsBf, int Kpad,
                     int C, const __nv_bfloat16* Wch, const __nv_bfloat16* Wcl, int rsW,
                     const float* gc, const float* bc,
                     int O, int rsH, int oOff){
        k_xx<<<(B_*N_)/256, 256>>>(XinF, C, rsF, xx);
        k_pd_mma<<<dim3(NTRI, 1, B_), 256, SMEMB>>>(Xh, Xl, rsBf, Kpad, xx, pdk);
        k_topk<<<dim3(N_, B_), 256>>>(pdk, idx);
        k_attn<<<dim3(N_/8, B_), 256>>>(XinF, C, rsF, idx, hh, hl, rsH);
        k_conv_mma<<<dim3(N_/128, (O+127)/128, B_), 256, SMEMB>>>(
            Wch, Wcl, rsW, gc, bc, hh, hl, rsH, rsH, O, cat, 512, oOff, cath, catl, 1);
    };

    stage(xt,        3,   xth,      xtl,      16,  16,  3,
          w1h, w1l, 32,  g1, b1,  64,  16,   0);
    stage(cat +   0, 512, cath+0,   catl+0,   512, 64,  64,
          w2h, w2l, 128, g2, b2,  64,  128,  64);
    stage(cat +  64, 512, cath+64,  catl+64,  512, 64,  64,
          w3h, w3l, 128, g3, b3, 128,  128, 128);
    stage(cat + 128, 512, cath+128, catl+128, 512, 128, 128,
          w4h, w4l, 256, g4, b4, 256,  256, 256);

    /* x5 = conv_bn(concat, W5) : C2=512, O=1024 */
    k_conv_mma<<<dim3(N_/128, 1024/128, B_), 256, SMEMB>>>(
        w5h, w5l, 512, g5, b5, cath, catl, 512, 512, 1024, x5, 1024, 0,
        (__nv_bfloat16*)0, (__nv_bfloat16*)0, 0);

    k_scores<<<(B_*N_)/8, 256>>>(x5, Watt, sc);
    k_attagg<<<dim3(1024/256, B_), 256>>>(x5, sc, att);
    k_ln<<<B_, 256>>>(att, ln_g, ln_b, attln);

    k_fc<<<(B_*512)/8, 256>>>(attln, Wl1, bl1, g6, b6, y1, 4096, 512, 1);
    k_fc<<<(B_*256)/8, 256>>>(y1,    Wl2, bl2, g7, b7, y2,  512, 256, 1);
    k_fc<<<(B_*40 + 7)/8, 256>>>(y2, Wl3, bl3, (const float*)0, (const float*)0,
                                 (float*)d_out, 256, 40, 0);
}

// round 11
// speedup vs baseline: 1.2541x; 1.1327x over previous
#include <cuda_runtime.h>
#include <cuda_bf16.h>

#define NEG    0.2f
#define BNS    0.9999950000374997f   /* 1/sqrt(1+1e-5) */
#define LNEPS  1e-5f
#define B_     16
#define N_     2048
#define KNN    20
#define NSEG   8

#define KCH   32                     /* K chunk */
#define STG   40960                  /* bytes per double-buffer stage */
#define SMEMB 81920
#define NTRI  136                    /* 16*17/2 upper-triangle tiles */

/* ------------- scratch (device globals; no runtime allocation) ------------- */
__device__ float g_xt  [B_*N_*3];
__device__ float g_cat [(size_t)B_*N_*512];
__device__ float g_x5  [(size_t)B_*N_*1024];
__device__ unsigned g_pd [(size_t)B_*N_*N_];      /* transformed order keys */
__device__ float g_xx  [B_*N_];
__device__ int   g_idx [B_*N_*KNN];
__device__ float g_sc  [B_*N_*4];
__device__ float g_attp[NSEG*B_*4096];
__device__ float g_attln[B_*4096];
__device__ float g_y1  [B_*512];
__device__ float g_y2  [B_*256];
__device__ __nv_bfloat16 g_xth[B_*N_*16];
__device__ __nv_bfloat16 g_xtl[B_*N_*16];
__device__ __nv_bfloat16 g_hh [(size_t)B_*N_*256];
__device__ __nv_bfloat16 g_hl [(size_t)B_*N_*256];
__device__ __nv_bfloat16 g_cath[(size_t)B_*N_*512];
__device__ __nv_bfloat16 g_catl[(size_t)B_*N_*512];
/* pre-split conv weights, padded to [Opad][rsW] */
__device__ __nv_bfloat16 g_w1h[128*32],    g_w1l[128*32];
__device__ __nv_bfloat16 g_w2h[128*128],   g_w2l[128*128];
__device__ __nv_bfloat16 g_w3h[128*128],   g_w3l[128*128];
__device__ __nv_bfloat16 g_w4h[256*256],   g_w4l[256*256];
__device__ __nv_bfloat16 g_w5h[1024*512],  g_w5l[1024*512];

__device__ __forceinline__ float lrelu(float v){ return v > 0.f ? v : NEG*v; }
__device__ __forceinline__ unsigned mkkey(float v){
    unsigned u = __float_as_uint(v);
    return (u & 0x80000000u) ? ~u : (u | 0x80000000u);
}

__device__ __forceinline__ unsigned smem_u32(const void* p){
    unsigned a;
    asm("{ .reg .u64 t; cvta.to.shared.u64 t, %1; cvt.u32.u64 %0, t; }":"=r"(a):"l"(p));
    return a;
}
#define LDMX4(r0,r1,r2,r3,a) \
    asm volatile("ldmatrix.sync.aligned.m8n8.x4.shared.b16 {%0,%1,%2,%3}, [%4];" \
        : "=r"(r0),"=r"(r1),"=r"(r2),"=r"(r3) : "r"(a))

__device__ __forceinline__ void mma_bf16(float* c, unsigned a0,unsigned a1,unsigned a2,unsigned a3,
                                         unsigned b0,unsigned b1){
    asm volatile("mma.sync.aligned.m16n8k16.row.col.f32.bf16.bf16.f32 "
        "{%0,%1,%2,%3},{%4,%5,%6,%7},{%8,%9},{%0,%1,%2,%3};"
        : "+f"(c[0]),"+f"(c[1]),"+f"(c[2]),"+f"(c[3])
        : "r"(a0),"r"(a1),"r"(a2),"r"(a3),"r"(b0),"r"(b1));
}

/* bf16 tile loader: 128 rows x 32 cols into smem, row pitch 80B */
__device__ __forceinline__ void ld_tile_bf16(char* sm, int off,
        const __nv_bfloat16* __restrict__ src, int row0, int rsIn, int k0, int Kpad, int tid){
    for(int i=tid;i<512;i+=256){
        int r=i>>2, q=i&3, k=k0+q*8;
        uint4 v = make_uint4(0,0,0,0);
        if(k < Kpad) v = *(const uint4*)(src + (size_t)(row0+r)*rsIn + k);
        *(uint4*)(sm + off + r*80 + q*16) = v;
    }
}

/* one K-chunk (32) of split-precision mma */
__device__ __forceinline__ void gemm_chunk(float (&acc)[4][4][4], unsigned base,
                                           int wm, int wn, int lane){
    int g = lane>>3, r = lane&7;
    #pragma unroll
    for(int h=0;h<2;h++){
        int k16 = h*16;
        unsigned ah[4][4], bh[4][2], bl[4][2];
        #pragma unroll
        for(int mt=0;mt<4;mt++){
            unsigned ad = base + (unsigned)((wm+mt*16+(g&1)*8+r)*80 + (k16+(g>>1)*8)*2);
            LDMX4(ah[mt][0],ah[mt][1],ah[mt][2],ah[mt][3], ad);
        }
        #pragma unroll
        for(int p=0;p<2;p++){
            unsigned bd = base + 20480u + (unsigned)((wn+p*16+(g>>1)*8+r)*80 + (k16+(g&1)*8)*2);
            LDMX4(bh[2*p][0],bh[2*p][1],bh[2*p+1][0],bh[2*p+1][1], bd);
        }
        #pragma unroll
        for(int mt=0;mt<4;mt++)
            #pragma unroll
            for(int nt=0;nt<4;nt++)
                mma_bf16(acc[mt][nt], ah[mt][0],ah[mt][1],ah[mt][2],ah[mt][3],
                         bh[nt][0],bh[nt][1]);
        #pragma unroll
        for(int p=0;p<2;p++){
            unsigned bd = base + 30720u + (unsigned)((wn+p*16+(g>>1)*8+r)*80 + (k16+(g&1)*8)*2);
            LDMX4(bl[2*p][0],bl[2*p][1],bl[2*p+1][0],bl[2*p+1][1], bd);
        }
        #pragma unroll
        for(int mt=0;mt<4;mt++)
            #pragma unroll
            for(int nt=0;nt<4;nt++)
                mma_bf16(acc[mt][nt], ah[mt][0],ah[mt][1],ah[mt][2],ah[mt][3],
                         bl[nt][0],bl[nt][1]);
        #pragma unroll
        for(int mt=0;mt<4;mt++){
            unsigned ad = base + 10240u + (unsigned)((wm+mt*16+(g&1)*8+r)*80 + (k16+(g>>1)*8)*2);
            LDMX4(ah[mt][0],ah[mt][1],ah[mt][2],ah[mt][3], ad);
        }
        #pragma unroll
        for(int mt=0;mt<4;mt++)
            #pragma unroll
            for(int nt=0;nt<4;nt++)
                mma_bf16(acc[mt][nt], ah[mt][0],ah[mt][1],ah[mt][2],ah[mt][3],
                         bh[nt][0],bh[nt][1]);
    }
}

/* ------------- weight pre-split: fp32 [O][C2] -> padded bf16 h/l ----------- */
__global__ void k_wsplit(const float* __restrict__ W, int O, int C2,
                         int Opad, int rsW,
                         __nv_bfloat16* __restrict__ Wh, __nv_bfloat16* __restrict__ Wl){
    int i = blockIdx.x*256 + threadIdx.x;
    if(i >= Opad*rsW) return;
    int o = i / rsW, k = i % rsW;
    float v = (o < O && k < C2) ? W[(size_t)o*C2 + k] : 0.f;
    __nv_bfloat16 h = __float2bfloat16(v);
    Wh[i] = h;
    Wl[i] = __float2bfloat16(v - __bfloat162float(h));
}

/* ------------------ transpose input + bf16 split --------------------------- */
__global__ void k_transpose_in(const float* __restrict__ x, float* __restrict__ xt,
                               __nv_bfloat16* __restrict__ xh, __nv_bfloat16* __restrict__ xl){
    int i = blockIdx.x*blockDim.x + threadIdx.x;
    if(i >= B_*N_) return;
    int b = i / N_, n = i % N_;
    #pragma unroll
    for(int c=0;c<3;c++){
        float v = x[((size_t)b*3+c)*N_ + n];
        xt[i*3+c] = v;
        __nv_bfloat16 h = __float2bfloat16(v);
        xh[i*16+c] = h;
        xl[i*16+c] = __float2bfloat16(v - __bfloat162float(h));
    }
    #pragma unroll
    for(int c=3;c<16;c++){ xh[i*16+c]=__float2bfloat16(0.f); xl[i*16+c]=__float2bfloat16(0.f); }
}

/* ---------------------- per-point squared norm ----------------------------- */
__global__ void k_xx(const float* __restrict__ xt, int C, int rs, float* __restrict__ xx){
    int i = blockIdx.x*blockDim.x + threadIdx.x;
    if(i >= B_*N_) return;
    const float* p = xt + (size_t)i*rs;
    float s = 0.f;
    for(int c=0;c<C;c++){ float v = p[c]; s += v*v; }
    xx[i] = s;
}

/* ---- pd keys, symmetric: upper-triangle tiles + mirrored smem transpose --- */
__global__ __launch_bounds__(256,2) void k_pd_mma(
        const __nv_bfloat16* __restrict__ Xh, const __nv_bfloat16* __restrict__ Xl,
        int rsIn, int Kpad, const float* __restrict__ xx, unsigned* __restrict__ pdk){
    extern __shared__ char smem[];
    unsigned sb = smem_u32(smem);
    int b = blockIdx.z;
    int ti = 0, rem = blockIdx.x;
    while(rem >= 16 - ti){ rem -= 16 - ti; ti++; }
    int tj = ti + rem;
    int n0 = ti*128, m0 = tj*128;
    bool diag = (ti == tj);
    int tid = threadIdx.x, wid = tid>>5, lane = tid&31;
    const __nv_bfloat16* Xhb = Xh + (size_t)b*N_*rsIn;
    const __nv_bfloat16* Xlb = Xl + (size_t)b*N_*rsIn;

    float acc[4][4][4];
    #pragma unroll
    for(int a=0;a<4;a++) for(int bq=0;bq<4;bq++) for(int cq=0;cq<4;cq++) acc[a][bq][cq]=0.f;

    int nch = (Kpad + KCH - 1)/KCH;
    ld_tile_bf16(smem, 0,     Xhb, n0, rsIn, 0, Kpad, tid);
    ld_tile_bf16(smem, 10240, Xlb, n0, rsIn, 0, Kpad, tid);
    ld_tile_bf16(smem, 20480, Xhb, m0, rsIn, 0, Kpad, tid);
    ld_tile_bf16(smem, 30720, Xlb, m0, rsIn, 0, Kpad, tid);
    __syncthreads();

    int wm = (wid>>2)*64, wn = (wid&3)*32;
    for(int c=0;c<nch;c++){
        int buf = c&1;
        if(c+1 < nch){
            int nb = (c+1)&1, k0 = (c+1)*KCH;
            ld_tile_bf16(smem, nb*STG+0,     Xhb, n0, rsIn, k0, Kpad, tid);
            ld_tile_bf16(smem, nb*STG+10240, Xlb, n0, rsIn, k0, Kpad, tid);
            ld_tile_bf16(smem, nb*STG+20480, Xhb, m0, rsIn, k0, Kpad, tid);
            ld_tile_bf16(smem, nb*STG+30720, Xlb, m0, rsIn, k0, Kpad, tid);
        }
        gemm_chunk(acc, sb + buf*STG, wm, wn, lane);
        __syncthreads();
    }

    const float* xxb = xx + b*N_;
    unsigned* sK = (unsigned*)smem;     /* 128x128 keys, pitch 129 words */
    int rr = lane>>2, cc = 2*(lane&3);
    #pragma unroll
    for(int mt=0;mt<4;mt++){
        int row = wm + mt*16 + rr;
        float xn0 = xxb[n0+row], xn8 = xxb[n0+row+8];
        #pragma unroll
        for(int nt=0;nt<4;nt++){
            int col = wn + nt*8 + cc;
            float xm0 = xxb[m0+col], xm1 = xxb[m0+col+1];
            uint2 u0, u1;
            u0.x = mkkey(2.f*acc[mt][nt][0] - xn0 - xm0);
            u0.y = mkkey(2.f*acc[mt][nt][1] - xn0 - xm1);
            u1.x = mkkey(2.f*acc[mt][nt][2] - xn8 - xm0);
            u1.y = mkkey(2.f*acc[mt][nt][3] - xn8 - xm1);
            if(diag){
                if(row   == col  ) u0.x = 0u;
                if(row   == col+1) u0.y = 0u;
                if(row+8 == col  ) u1.x = 0u;
                if(row+8 == col+1) u1.y = 0u;
            }
            *(uint2*)(pdk + ((size_t)b*N_ + n0+row  )*N_ + m0 + col) = u0;
            *(uint2*)(pdk + ((size_t)b*N_ + n0+row+8)*N_ + m0 + col) = u1;
            if(!diag){
                sK[ row   *129 + col  ] = u0.x;
                sK[ row   *129 + col+1] = u0.y;
                sK[(row+8)*129 + col  ] = u1.x;
                sK[(row+8)*129 + col+1] = u1.y;
            }
        }
    }
    if(!diag){
        __syncthreads();
        for(int i=0;i<16;i++){
            int r2 = wid + 8*i;
            size_t obase = ((size_t)b*N_ + m0 + r2)*N_ + n0;
            #pragma unroll
            for(int j=0;j<4;j++){
                int c2 = lane + 32*j;
                pdk[obase + c2] = sK[c2*129 + r2];
            }
        }
    }
}

/* ------- top-20 per row, 4-level 8-bit radix select on precomputed keys ---- */
__global__ void k_topk(const unsigned* __restrict__ pdk, int* __restrict__ idx){
    __shared__ unsigned hist[8][256];
    __shared__ unsigned sgs[256];
    __shared__ unsigned wtot[8], wabove[8];
    __shared__ int s_bin, s_above, s_outc, s_tiec;
    __shared__ int ties[2048];

    int b = blockIdx.y, n = blockIdx.x;
    int tid = threadIdx.x, lane = tid & 31, wp = tid >> 5;
    const unsigned* row = pdk + ((size_t)b*N_ + n)*N_;

    unsigned key[8];
    #pragma unroll
    for(int j=0;j<8;j++) key[j] = row[tid + 256*j];   /* self already 0 */

    unsigned prefix = 0, pmask = 0;
    int kneed = KNN;
    for(int level=0; level<4; level++){
        int shift = 24 - 8*level;
        #pragma unroll
        for(int w=0;w<8;w++) hist[w][tid] = 0;
        __syncthreads();
        #pragma unroll
        for(int j=0;j<8;j++){
            unsigned kk = key[j];
            if((kk & pmask) == prefix)
                atomicAdd(&hist[wp][(kk>>shift)&255u], 1u);
        }
        __syncthreads();
        unsigned c = 0;
        #pragma unroll
        for(int w=0;w<8;w++) c += hist[w][tid];
        unsigned s = c;
        #pragma unroll
        for(int off=1; off<32; off<<=1){
            unsigned o2 = __shfl_down_sync(0xffffffffu, s, off);
            if(lane + off < 32) s += o2;
        }
        if(lane==0) wtot[wp] = s;
        __syncthreads();
        if(tid==0){
            unsigned run=0;
            for(int w=7;w>=0;w--){ wabove[w]=run; run+=wtot[w]; }
        }
        __syncthreads();
        unsigned S = s + wabove[wp];
        sgs[tid] = S;
        __syncthreads();
        unsigned Snext = (tid<255) ? sgs[tid+1] : 0u;
        if(S >= (unsigned)kneed && Snext < (unsigned)kneed){
            s_bin = tid; s_above = (int)Snext;
        }
        __syncthreads();
        prefix |= ((unsigned)s_bin) << shift;
        pmask  |= 0xFFu << shift;
        kneed  -= s_above;
        __syncthreads();
    }

    unsigned T = prefix;
    int rem = kneed;                      /* # of ==T to take, >=1 */
    int* op = idx + ((b*N_)+n)*KNN;
    if(tid==0){ s_outc = 0; s_tiec = 0; }
    __syncthreads();
    #pragma unroll
    for(int j=0;j<8;j++){
        unsigned kk = key[j]; int m = tid + 256*j;
        if(kk > T){
            int p = atomicAdd(&s_outc, 1);
            op[p] = m;
        } else if(kk == T){
            int p = atomicAdd(&s_tiec, 1);
            ties[p] = m;
        }
    }
    __syncthreads();
    int cg = s_outc;
    if(wp==0){
        int tc = s_tiec;
        for(int r=0;r<rem;r++){
            int best = 0x7fffffff, bpos = -1;
            for(int t2=lane; t2<tc; t2+=32){
                int v = ties[t2];
                if(v < best){ best = v; bpos = t2; }
            }
            #pragma unroll
            for(int off=16; off>0; off>>=1){
                int ov = __shfl_xor_sync(0xffffffffu, best, off);
                int opo= __shfl_xor_sync(0xffffffffu, bpos, off);
                if(ov < best){ best = ov; bpos = opo; }
            }
            if(lane==0){ op[cg + r] = best; ties[bpos] = 0x7fffffff; }
            __syncwarp();
        }
    }
}

/* -------- conv1x1 (+BN+lrelu), pre-split bf16 weights; emits bf16 twins ---- */
__global__ __launch_bounds__(256,2) void k_conv_mma(
        const __nv_bfloat16* __restrict__ Wh, const __nv_bfloat16* __restrict__ Wl, int rsW,
        const float* __restrict__ gg, const float* __restrict__ bb,
        const __nv_bfloat16* __restrict__ Hh, const __nv_bfloat16* __restrict__ Hl,
        int rsB, int Kpad, int O,
        float* __restrict__ yout, int rsOut, int oOff,
        __nv_bfloat16* __restrict__ couth, __nv_bfloat16* __restrict__ coutl, int wbf){
    extern __shared__ char smem[];
    unsigned sb = smem_u32(smem);
    int b = blockIdx.z, n0 = blockIdx.x*128, o0 = blockIdx.y*128;
    int tid = threadIdx.x, wid = tid>>5, lane = tid&31;
    const __nv_bfloat16* Hhb = Hh + (size_t)b*N_*rsB;
    const __nv_bfloat16* Hlb = Hl + (size_t)b*N_*rsB;

    float acc[4][4][4];
    #pragma unroll
    for(int a=0;a<4;a++) for(int bq=0;bq<4;bq++) for(int cq=0;cq<4;cq++) acc[a][bq][cq]=0.f;

    int nch = (Kpad + KCH - 1)/KCH;
    ld_tile_bf16(smem, 0,     Wh,  o0, rsW, 0, Kpad, tid);
    ld_tile_bf16(smem, 10240, Wl,  o0, rsW, 0, Kpad, tid);
    ld_tile_bf16(smem, 20480, Hhb, n0, rsB, 0, Kpad, tid);
    ld_tile_bf16(smem, 30720, Hlb, n0, rsB, 0, Kpad, tid);
    __syncthreads();

    int wm = (wid>>2)*64, wn = (wid&3)*32;
    for(int c=0;c<nch;c++){
        int buf = c&1;
        if(c+1 < nch){
            int nb = (c+1)&1, k0 = (c+1)*KCH;
            ld_tile_bf16(smem, nb*STG+0,     Wh,  o0, rsW, k0, Kpad, tid);
            ld_tile_bf16(smem, nb*STG+10240, Wl,  o0, rsW, k0, Kpad, tid);
            ld_tile_bf16(smem, nb*STG+20480, Hhb, n0, rsB, k0, Kpad, tid);
            ld_tile_bf16(smem, nb*STG+30720, Hlb, n0, rsB, k0, Kpad, tid);
        }
        gemm_chunk(acc, sb + buf*STG, wm, wn, lane);
        __syncthreads();
    }

    float* sC = (float*)smem;
    int rr = lane>>2, cc = 2*(lane&3);
    #pragma unroll
    for(int mt=0;mt<4;mt++){
        int row = wm + mt*16 + rr;
        #pragma unroll
        for(int nt=0;nt<4;nt++){
            int col = wn + nt*8 + cc;
            sC[ row   *129 + col  ] = acc[mt][nt][0];
            sC[ row   *129 + col+1] = acc[mt][nt][1];
            sC[(row+8)*129 + col  ] = acc[mt][nt][2];
            sC[(row+8)*129 + col+1] = acc[mt][nt][3];
        }
    }
    __syncthreads();

    int Olocal = O - o0; if(Olocal > 128) Olocal = 128;
    float scv[4], bsv[4];
    #pragma unroll
    for(int j=0;j<4;j++){
        int o = lane + 32*j;
        scv[j] = (o<Olocal) ? BNS*gg[o0+o] : 0.f;
        bsv[j] = (o<Olocal) ? bb[o0+o]     : 0.f;
    }
    for(int i=0;i<16;i++){
        int n = wid + 8*i;
        size_t rbase = (size_t)(b*N_ + n0 + n);
        #pragma unroll
        for(int j=0;j<4;j++){
            int o = lane + 32*j;
            if(o < Olocal){
                float y = lrelu(fmaf(sC[o*129+n], scv[j], bsv[j]));
                yout[rbase*rsOut + oOff + o0 + o] = y;
                if(wbf){
                    __nv_bfloat16 h = __float2bfloat16(y);
                    couth[rbase*512 + oOff + o0 + o] = h;
                    coutl[rbase*512 + oOff + o0 + o] = __float2bfloat16(y - __bfloat162float(h));
                }
            }
        }
    }
}

/* ---- attention aggregate: writes bf16 hi/lo h = [q, softmax.(key-q)] ------ */
__global__ void k_attn(const float* __restrict__ xt, int C, int rs,
                       const int* __restrict__ idx,
                       __nv_bfloat16* __restrict__ hH, __nv_bfloat16* __restrict__ hL,
                       int rsH){
    int b    = blockIdx.y;
    int warp = threadIdx.x >> 5, lane = threadIdx.x & 31;
    int n    = blockIdx.x*8 + warp;
    const float* Xb = xt + (size_t)b*N_*rs;
    float q[4];
    #pragma unroll
    for(int j=0;j<4;j++){
        int c = lane + 32*j;
        q[j] = (c<C) ? Xb[(size_t)n*rs + c] : 0.f;
    }
    const int* ip = idx + ((b*N_)+n)*KNN;
    int   nbr[KNN];
    float lg [KNN];
    for(int k=0;k<KNN;k++){
        int m = ip[k];
        nbr[k] = m;
        const float* kp = Xb + (size_t)m*rs;
        float p = 0.f;
        #pragma unroll
        for(int j=0;j<4;j++){
            int c = lane + 32*j;
            if(c<C) p += q[j]*kp[c];
        }
        #pragma unroll
        for(int o=16;o>0;o>>=1) p += __shfl_xor_sync(0xffffffffu,p,o);
        lg[k] = p;
    }
    float mx = -3e38f;
    #pragma unroll
    for(int k=0;k<KNN;k++) mx = fmaxf(mx, lg[k]);
    float Z = 0.f;
    #pragma unroll
    for(int k=0;k<KNN;k++){ lg[k] = expf(lg[k]-mx); Z += lg[k]; }
    float inv = 1.f/Z;
    size_t base = (size_t)(b*N_+n)*rsH;
    #pragma unroll
    for(int j=0;j<4;j++){
        int c = lane + 32*j;
        if(c<C){
            float f = 0.f;
            for(int k=0;k<KNN;k++) f += lg[k]*(Xb[(size_t)nbr[k]*rs + c] - q[j]);
            f *= inv;
            __nv_bfloat16 qh = __float2bfloat16(q[j]);
            hH[base + c]   = qh;
            hL[base + c]   = __float2bfloat16(q[j] - __bfloat162float(qh));
            __nv_bfloat16 fh = __float2bfloat16(f);
            hH[base + C + c] = fh;
            hL[base + C + c] = __float2bfloat16(f - __bfloat162float(fh));
        }
    }
    int extra = rsH - 2*C;
    if(extra > 0 && lane < extra){
        hH[base + 2*C + lane] = __float2bfloat16(0.f);
        hL[base + 2*C + lane] = __float2bfloat16(0.f);
    }
}

/* ------------ scores[b,n,h] = lrelu(sum_e x5[b,n,e] Watt[h,e]) ------------- */
__global__ void k_scores(const float* __restrict__ x5, const float* __restrict__ Watt,
                         float* __restrict__ sc){
    int gw   = (blockIdx.x*256 + threadIdx.x) >> 5;
    int lane = threadIdx.x & 31;
    if(gw >= B_*N_) return;
    const float* xp = x5 + (size_t)gw*1024;
    float a0=0,a1=0,a2=0,a3=0;
    for(int e=lane;e<1024;e+=32){
        float v = xp[e];
        a0 += v*Watt[e];
        a1 += v*Watt[1024+e];
        a2 += v*Watt[2048+e];
        a3 += v*Watt[3072+e];
    }
    #pragma unroll
    for(int o=16;o>0;o>>=1){
        a0 += __shfl_xor_sync(0xffffffffu,a0,o);
        a1 += __shfl_xor_sync(0xffffffffu,a1,o);
        a2 += __shfl_xor_sync(0xffffffffu,a2,o);
        a3 += __shfl_xor_sync(0xffffffffu,a3,o);
    }
    if(lane==0){
        sc[(size_t)gw*4+0] = lrelu(a0);
        sc[(size_t)gw*4+1] = lrelu(a1);
        sc[(size_t)gw*4+2] = lrelu(a2);
        sc[(size_t)gw*4+3] = lrelu(a3);
    }
}

/* --- attp[seg,b,h*1024+e] = sum_{n in seg} x5[b,n,e]*sc[b,n,h], 8 segs ----- */
__global__ void k_attagg(const float* __restrict__ x5, const float* __restrict__ sc,
                         float* __restrict__ attp){
    __shared__ float ssc[256*4];
    int b = blockIdx.y, seg = blockIdx.z;
    int e = blockIdx.x*256 + threadIdx.x;
    int n0 = seg*256;
    float a0=0,a1=0,a2=0,a3=0;
    for(int i=threadIdx.x;i<1024;i+=256)
        ssc[i] = sc[((size_t)b*N_+n0)*4 + i];
    __syncthreads();
    for(int nn=0;nn<256;nn++){
        float v = x5[((size_t)(b*N_+n0+nn))*1024 + e];
        a0 += v*ssc[nn*4+0];
        a1 += v*ssc[nn*4+1];
        a2 += v*ssc[nn*4+2];
        a3 += v*ssc[nn*4+3];
    }
    float* op = attp + ((size_t)seg*B_ + b)*4096;
    op[   0 + e] = a0;
    op[1024 + e] = a1;
    op[2048 + e] = a2;
    op[3072 + e] = a3;
}

/* ------------- LayerNorm(4096) over summed partials + lrelu ---------------- */
__global__ void k_ln(const float* __restrict__ attp, const float* __restrict__ g,
                     const float* __restrict__ bt, float* __restrict__ out){
    __shared__ float red[256];
    __shared__ float sv[4096];
    int b = blockIdx.x, tid = threadIdx.x;
    float s=0.f;
    for(int i=tid;i<4096;i+=256){
        float a = 0.f;
        #pragma unroll
        for(int seg=0;seg<NSEG;seg++)
            a += attp[((size_t)seg*B_ + b)*4096 + i];
        sv[i] = a;
        s += a;
    }
    red[tid]=s; __syncthreads();
    for(int st=128;st>0;st>>=1){ if(tid<st) red[tid]+=red[tid+st]; __syncthreads(); }
    float mean = red[0]*(1.f/4096.f); __syncthreads();
    float v=0.f;
    for(int i=tid;i<4096;i+=256){ float d=sv[i]-mean; v+=d*d; }
    red[tid]=v; __syncthreads();
    for(int st=128;st>0;st>>=1){ if(tid<st) red[tid]+=red[tid+st]; __syncthreads(); }
    float inv = 1.f/sqrtf(red[0]*(1.f/4096.f) + LNEPS);
    for(int i=tid;i<4096;i+=256){
        float y = (sv[i]-mean)*inv*g[i] + bt[i];
        out[b*4096+i] = lrelu(y);
    }
}

/* ------------- warp-per-output fully-connected (+opt bnaff+lrelu) ---------- */
__global__ void k_fc(const float* __restrict__ A, const float* __restrict__ W,
                     const float* __restrict__ bias, const float* __restrict__ g,
                     const float* __restrict__ bt, float* __restrict__ out,
                     int K, int O, int mode){
    int gw   = (blockIdx.x*256 + threadIdx.x) >> 5;
    int lane = threadIdx.x & 31;
    if(gw >= B_*O) return;
    int b = gw / O, o = gw % O;
    const float* a = A + (size_t)b*K;
    const float* w = W + (size_t)o*K;
    float s=0.f;
    for(int k2=lane;k2<K;k2+=32) s += a[k2]*w[k2];
    #pragma unroll
    for(int off=16;off>0;off>>=1) s += __shfl_xor_sync(0xffffffffu,s,off);
    if(lane==0){
        s += bias[o];
        if(mode){ s = s*BNS*g[o] + bt[o]; s = lrelu(s); }
        out[(size_t)b*O+o] = s;
    }
}

/* ------------------------------- launcher ---------------------------------- */
extern "C" void kernel_launch(void* const* d_in, const int* in_sizes, int n_in,
                              void* d_out, int out_size){
    const float* x    = (const float*)d_in[0];
    const float* W1   = (const float*)d_in[1];
    const float* g1   = (const float*)d_in[2];
    const float* b1   = (const float*)d_in[3];
    const float* W2   = (const float*)d_in[4];
    const float* g2   = (const float*)d_in[5];
    const float* b2   = (const float*)d_in[6];
    const float* W3   = (const float*)d_in[7];
    const float* g3   = (const float*)d_in[8];
    const float* b3   = (const float*)d_in[9];
    const float* W4   = (const float*)d_in[10];
    const float* g4   = (const float*)d_in[11];
    const float* b4   = (const float*)d_in[12];
    const float* W5   = (const float*)d_in[13];
    const float* g5   = (const float*)d_in[14];
    const float* b5   = (const float*)d_in[15];
    const float* Watt = (const float*)d_in[16];
    const float* ln_g = (const float*)d_in[17];
    const float* ln_b = (const float*)d_in[18];
    const float* Wl1  = (const float*)d_in[19];
    const float* bl1  = (const float*)d_in[20];
    const float* g6   = (const float*)d_in[21];
    const float* b6   = (const float*)d_in[22];
    const float* Wl2  = (const float*)d_in[23];
    const float* bl2  = (const float*)d_in[24];
    const float* g7   = (const float*)d_in[25];
    const float* b7   = (const float*)d_in[26];
    const float* Wl3  = (const float*)d_in[27];
    const float* bl3  = (const float*)d_in[28];

    float *xt, *cat, *x5, *xx, *sc, *attp, *attln, *y1, *y2;
    unsigned* pdk;
    int* idx;
    __nv_bfloat16 *xth, *xtl, *hh, *hl, *cath, *catl;
    __nv_bfloat16 *w1h,*w1l,*w2h,*w2l,*w3h,*w3l,*w4h,*w4l,*w5h,*w5l;
    cudaGetSymbolAddress((void**)&xt,   g_xt);
    cudaGetSymbolAddress((void**)&cat,  g_cat);
    cudaGetSymbolAddress((void**)&x5,   g_x5);
    cudaGetSymbolAddress((void**)&pdk,  g_pd);
    cudaGetSymbolAddress((void**)&xx,   g_xx);
    cudaGetSymbolAddress((void**)&idx,  g_idx);
    cudaGetSymbolAddress((void**)&sc,   g_sc);
    cudaGetSymbolAddress((void**)&attp, g_attp);
    cudaGetSymbolAddress((void**)&attln,g_attln);
    cudaGetSymbolAddress((void**)&y1,   g_y1);
    cudaGetSymbolAddress((void**)&y2,   g_y2);
    cudaGetSymbolAddress((void**)&xth,  g_xth);
    cudaGetSymbolAddress((void**)&xtl,  g_xtl);
    cudaGetSymbolAddress((void**)&hh,   g_hh);
    cudaGetSymbolAddress((void**)&hl,   g_hl);
    cudaGetSymbolAddress((void**)&cath, g_cath);
    cudaGetSymbolAddress((void**)&catl, g_catl);
    cudaGetSymbolAddress((void**)&w1h,  g_w1h);
    cudaGetSymbolAddress((void**)&w1l,  g_w1l);
    cudaGetSymbolAddress((void**)&w2h,  g_w2h);
    cudaGetSymbolAddress((void**)&w2l,  g_w2l);
    cudaGetSymbolAddress((void**)&w3h,  g_w3h);
    cudaGetSymbolAddress((void**)&w3l,  g_w3l);
    cudaGetSymbolAddress((void**)&w4h,  g_w4h);
    cudaGetSymbolAddress((void**)&w4l,  g_w4l);
    cudaGetSymbolAddress((void**)&w5h,  g_w5h);
    cudaGetSymbolAddress((void**)&w5l,  g_w5l);

    cudaFuncSetAttribute(k_pd_mma,   cudaFuncAttributeMaxDynamicSharedMemorySize, SMEMB);
    cudaFuncSetAttribute(k_conv_mma, cudaFuncAttributeMaxDynamicSharedMemorySize, SMEMB);

    /* weight pre-split (padded Opad x rsW) */
    k_wsplit<<<(128*32  + 255)/256, 256>>>(W1,   64,   6, 128,  32, w1h, w1l);
    k_wsplit<<<(128*128 + 255)/256, 256>>>(W2,   64, 128, 128, 128, w2h, w2l);
    k_wsplit<<<(128*128 + 255)/256, 256>>>(W3,  128, 128, 128, 128, w3h, w3l);
    k_wsplit<<<(256*256 + 255)/256, 256>>>(W4,  256, 256, 256, 256, w4h, w4l);
    k_wsplit<<<(1024*512+ 255)/256, 256>>>(W5, 1024, 512,1024, 512, w5h, w5l);

    k_transpose_in<<<(B_*N_)/256, 256>>>(x, xt, xth, xtl);

    auto stage = [&](const float* XinF, int rsF,
                     const __nv_bfloat16* Xh, const __nv_bfloat16* Xl, int rsBf, int Kpad,
                     int C, const __nv_bfloat16* Wch, const __nv_bfloat16* Wcl, int rsW,
                     const float* gc, const float* bc,
                     int O, int rsH, int oOff){
        k_xx<<<(B_*N_)/256, 256>>>(XinF, C, rsF, xx);
        k_pd_mma<<<dim3(NTRI, 1, B_), 256, SMEMB>>>(Xh, Xl, rsBf, Kpad, xx, pdk);
        k_topk<<<dim3(N_, B_), 256>>>(pdk, idx);
        k_attn<<<dim3(N_/8, B_), 256>>>(XinF, C, rsF, idx, hh, hl, rsH);
        k_conv_mma<<<dim3(N_/128, (O+127)/128, B_), 256, SMEMB>>>(
            Wch, Wcl, rsW, gc, bc, hh, hl, rsH, rsH, O, cat, 512, oOff, cath, catl, 1);
    };

    stage(xt,        3,   xth,      xtl,      16,  16,  3,
          w1h, w1l, 32,  g1, b1,  64,  16,   0);
    stage(cat +   0, 512, cath+0,   catl+0,   512, 64,  64,
          w2h, w2l, 128, g2, b2,  64,  128,  64);
    stage(cat +  64, 512, cath+64,  catl+64,  512, 64,  64,
          w3h, w3l, 128, g3, b3, 128,  128, 128);
    stage(cat + 128, 512, cath+128, catl+128, 512, 128, 128,
          w4h, w4l, 256, g4, b4, 256,  256, 256);

    /* x5 = conv_bn(concat, W5) : C2=512, O=1024 */
    k_conv_mma<<<dim3(N_/128, 1024/128, B_), 256, SMEMB>>>(
        w5h, w5l, 512, g5, b5, cath, catl, 512, 512, 1024, x5, 1024, 0,
        (__nv_bfloat16*)0, (__nv_bfloat16*)0, 0);

    k_scores<<<(B_*N_)/8, 256>>>(x5, Watt, sc);
    k_attagg<<<dim3(1024/256, B_, NSEG), 256>>>(x5, sc, attp);
    k_ln<<<B_, 256>>>(attp, ln_g, ln_b, attln);

    k_fc<<<(B_*512)/8, 256>>>(attln, Wl1, bl1, g6, b6, y1, 4096, 512, 1);
    k_fc<<<(B_*256)/8, 256>>>(y1,    Wl2, bl2, g7, b7, y2,  512, 256, 1);
    k_fc<<<(B_*40 + 7)/8, 256>>>(y2, Wl3, bl3, (const float*)0, (const float*)0,
                                 (float*)d_out, 256, 40, 0);
}

// round 12
// speedup vs baseline: 1.4135x; 1.1271x over previous
#include <cuda_runtime.h>
#include <cuda_bf16.h>

#define NEG    0.2f
#define BNS    0.9999950000374997f   /* 1/sqrt(1+1e-5) */
#define LNEPS  1e-5f
#define B_     16
#define N_     2048
#define KNN    20
#define NSEG   8

#define KCH   32                     /* K chunk */
#define STG   40960                  /* bytes per double-buffer stage */
#define SMEMB 81920
#define NTRI  136                    /* 16*17/2 upper-triangle tiles */

/* ------------- scratch (device globals; no runtime allocation) ------------- */
__device__ float g_xt  [B_*N_*3];
__device__ float g_cat [(size_t)B_*N_*512];
__device__ float g_x5  [(size_t)B_*N_*1024];
__device__ unsigned g_pd [(size_t)B_*N_*N_];      /* transformed order keys */
__device__ float g_xx  [B_*N_];
__device__ int   g_idx [B_*N_*KNN];
__device__ float g_sc  [B_*N_*4];
__device__ float g_attp[NSEG*B_*4096];
__device__ float g_attln[B_*4096];
__device__ float g_y1  [B_*512];
__device__ float g_y2  [B_*256];
__device__ __nv_bfloat16 g_xth[B_*N_*16];
__device__ __nv_bfloat16 g_xtl[B_*N_*16];
__device__ __nv_bfloat16 g_hh [(size_t)B_*N_*256];
__device__ __nv_bfloat16 g_hl [(size_t)B_*N_*256];
__device__ __nv_bfloat16 g_cath[(size_t)B_*N_*512];
__device__ __nv_bfloat16 g_catl[(size_t)B_*N_*512];
/* pre-split conv weights, padded to [Opad][rsW] */
__device__ __nv_bfloat16 g_w1h[128*32],    g_w1l[128*32];
__device__ __nv_bfloat16 g_w2h[128*128],   g_w2l[128*128];
__device__ __nv_bfloat16 g_w3h[128*128],   g_w3l[128*128];
__device__ __nv_bfloat16 g_w4h[256*256],   g_w4l[256*256];
__device__ __nv_bfloat16 g_w5h[1024*512],  g_w5l[1024*512];

__device__ __forceinline__ float lrelu(float v){ return v > 0.f ? v : NEG*v; }
__device__ __forceinline__ unsigned mkkey(float v){
    unsigned u = __float_as_uint(v);
    return (u & 0x80000000u) ? ~u : (u | 0x80000000u);
}

__device__ __forceinline__ unsigned smem_u32(const void* p){
    unsigned a;
    asm("{ .reg .u64 t; cvta.to.shared.u64 t, %1; cvt.u32.u64 %0, t; }":"=r"(a):"l"(p));
    return a;
}
#define LDMX4(r0,r1,r2,r3,a) \
    asm volatile("ldmatrix.sync.aligned.m8n8.x4.shared.b16 {%0,%1,%2,%3}, [%4];" \
        : "=r"(r0),"=r"(r1),"=r"(r2),"=r"(r3) : "r"(a))

__device__ __forceinline__ void mma_bf16(float* c, unsigned a0,unsigned a1,unsigned a2,unsigned a3,
                                         unsigned b0,unsigned b1){
    asm volatile("mma.sync.aligned.m16n8k16.row.col.f32.bf16.bf16.f32 "
        "{%0,%1,%2,%3},{%4,%5,%6,%7},{%8,%9},{%0,%1,%2,%3};"
        : "+f"(c[0]),"+f"(c[1]),"+f"(c[2]),"+f"(c[3])
        : "r"(a0),"r"(a1),"r"(a2),"r"(a3),"r"(b0),"r"(b1));
}

#define CP_COMMIT() asm volatile("cp.async.commit_group;":::"memory")
#define CP_WAIT1()  asm volatile("cp.async.wait_group 1;":::"memory")
#define CP_WAIT0()  asm volatile("cp.async.wait_group 0;":::"memory")

/* async bf16 tile loader: 128 rows x 32 cols, row pitch 80B, zero-fill tail */
__device__ __forceinline__ void cp_tile_bf16(unsigned dstBase,
        const __nv_bfloat16* __restrict__ src, int row0, int rsIn, int k0, int Kpad, int tid){
    for(int i=tid;i<512;i+=256){
        int r=i>>2, q=i&3, k=k0+q*8;
        unsigned dst = dstBase + (unsigned)(r*80 + q*16);
        int ok = (k < Kpad);
        const __nv_bfloat16* g = ok ? (src + (size_t)(row0+r)*rsIn + k) : src;
        int sz = ok ? 16 : 0;
        asm volatile("cp.async.cg.shared.global [%0], [%1], 16, %2;"
                     :: "r"(dst), "l"(g), "r"(sz));
    }
}

/* one K-chunk (32) of split-precision mma, absolute smem region addrs */
__device__ __forceinline__ void gemm_chunk(float (&acc)[4][4][4],
        unsigned ahB, unsigned alB, unsigned bhB, unsigned blB,
        int wm, int wn, int lane){
    int g = lane>>3, r = lane&7;
    #pragma unroll
    for(int h=0;h<2;h++){
        int k16 = h*16;
        unsigned ah[4][4], bh[4][2], bl[4][2];
        #pragma unroll
        for(int mt=0;mt<4;mt++){
            unsigned ad = ahB + (unsigned)((wm+mt*16+(g&1)*8+r)*80 + (k16+(g>>1)*8)*2);
            LDMX4(ah[mt][0],ah[mt][1],ah[mt][2],ah[mt][3], ad);
        }
        #pragma unroll
        for(int p=0;p<2;p++){
            unsigned bd = bhB + (unsigned)((wn+p*16+(g>>1)*8+r)*80 + (k16+(g&1)*8)*2);
            LDMX4(bh[2*p][0],bh[2*p][1],bh[2*p+1][0],bh[2*p+1][1], bd);
        }
        #pragma unroll
        for(int mt=0;mt<4;mt++)
            #pragma unroll
            for(int nt=0;nt<4;nt++)
                mma_bf16(acc[mt][nt], ah[mt][0],ah[mt][1],ah[mt][2],ah[mt][3],
                         bh[nt][0],bh[nt][1]);
        #pragma unroll
        for(int p=0;p<2;p++){
            unsigned bd = blB + (unsigned)((wn+p*16+(g>>1)*8+r)*80 + (k16+(g&1)*8)*2);
            LDMX4(bl[2*p][0],bl[2*p][1],bl[2*p+1][0],bl[2*p+1][1], bd);
        }
        #pragma unroll
        for(int mt=0;mt<4;mt++)
            #pragma unroll
            for(int nt=0;nt<4;nt++)
                mma_bf16(acc[mt][nt], ah[mt][0],ah[mt][1],ah[mt][2],ah[mt][3],
                         bl[nt][0],bl[nt][1]);
        #pragma unroll
        for(int mt=0;mt<4;mt++){
            unsigned ad = alB + (unsigned)((wm+mt*16+(g&1)*8+r)*80 + (k16+(g>>1)*8)*2);
            LDMX4(ah[mt][0],ah[mt][1],ah[mt][2],ah[mt][3], ad);
        }
        #pragma unroll
        for(int mt=0;mt<4;mt++)
            #pragma unroll
            for(int nt=0;nt<4;nt++)
                mma_bf16(acc[mt][nt], ah[mt][0],ah[mt][1],ah[mt][2],ah[mt][3],
                         bh[nt][0],bh[nt][1]);
    }
}

/* ------------- weight pre-split: fp32 [O][C2] -> padded bf16 h/l ----------- */
__global__ void k_wsplit(const float* __restrict__ W, int O, int C2,
                         int Opad, int rsW,
                         __nv_bfloat16* __restrict__ Wh, __nv_bfloat16* __restrict__ Wl){
    int i = blockIdx.x*256 + threadIdx.x;
    if(i >= Opad*rsW) return;
    int o = i / rsW, k = i % rsW;
    float v = (o < O && k < C2) ? W[(size_t)o*C2 + k] : 0.f;
    __nv_bfloat16 h = __float2bfloat16(v);
    Wh[i] = h;
    Wl[i] = __float2bfloat16(v - __bfloat162float(h));
}

/* ------------------ transpose input + bf16 split --------------------------- */
__global__ void k_transpose_in(const float* __restrict__ x, float* __restrict__ xt,
                               __nv_bfloat16* __restrict__ xh, __nv_bfloat16* __restrict__ xl){
    int i = blockIdx.x*blockDim.x + threadIdx.x;
    if(i >= B_*N_) return;
    int b = i / N_, n = i % N_;
    #pragma unroll
    for(int c=0;c<3;c++){
        float v = x[((size_t)b*3+c)*N_ + n];
        xt[i*3+c] = v;
        __nv_bfloat16 h = __float2bfloat16(v);
        xh[i*16+c] = h;
        xl[i*16+c] = __float2bfloat16(v - __bfloat162float(h));
    }
    #pragma unroll
    for(int c=3;c<16;c++){ xh[i*16+c]=__float2bfloat16(0.f); xl[i*16+c]=__float2bfloat16(0.f); }
}

/* ---------------------- per-point squared norm ----------------------------- */
__global__ void k_xx(const float* __restrict__ xt, int C, int rs, float* __restrict__ xx){
    int i = blockIdx.x*blockDim.x + threadIdx.x;
    if(i >= B_*N_) return;
    const float* p = xt + (size_t)i*rs;
    float s = 0.f;
    for(int c=0;c<C;c++){ float v = p[c]; s += v*v; }
    xx[i] = s;
}

/* ---- pd keys, symmetric: upper-triangle tiles + mirrored smem transpose --- */
__global__ __launch_bounds__(256,2) void k_pd_mma(
        const __nv_bfloat16* __restrict__ Xh, const __nv_bfloat16* __restrict__ Xl,
        int rsIn, int Kpad, const float* __restrict__ xx, unsigned* __restrict__ pdk){
    extern __shared__ char smem[];
    unsigned sb = smem_u32(smem);
    int b = blockIdx.z;
    int ti = 0, rem = blockIdx.x;
    while(rem >= 16 - ti){ rem -= 16 - ti; ti++; }
    int tj = ti + rem;
    int n0 = ti*128, m0 = tj*128;
    bool diag = (ti == tj);
    int tid = threadIdx.x, wid = tid>>5, lane = tid&31;
    const __nv_bfloat16* Xhb = Xh + (size_t)b*N_*rsIn;
    const __nv_bfloat16* Xlb = Xl + (size_t)b*N_*rsIn;

    float acc[4][4][4];
    #pragma unroll
    for(int a=0;a<4;a++) for(int bq=0;bq<4;bq++) for(int cq=0;cq<4;cq++) acc[a][bq][cq]=0.f;

    int nch = (Kpad + KCH - 1)/KCH;
    cp_tile_bf16(sb+0,     Xhb, n0, rsIn, 0, Kpad, tid);
    cp_tile_bf16(sb+10240, Xlb, n0, rsIn, 0, Kpad, tid);
    if(!diag){
        cp_tile_bf16(sb+20480, Xhb, m0, rsIn, 0, Kpad, tid);
        cp_tile_bf16(sb+30720, Xlb, m0, rsIn, 0, Kpad, tid);
    }
    CP_COMMIT();

    int wm = (wid>>2)*64, wn = (wid&3)*32;
    for(int c=0;c<nch;c++){
        unsigned cb = sb + (unsigned)((c&1)*STG);
        if(c+1 < nch){
            unsigned nb = sb + (unsigned)(((c+1)&1)*STG);
            int k0 = (c+1)*KCH;
            cp_tile_bf16(nb+0,     Xhb, n0, rsIn, k0, Kpad, tid);
            cp_tile_bf16(nb+10240, Xlb, n0, rsIn, k0, Kpad, tid);
            if(!diag){
                cp_tile_bf16(nb+20480, Xhb, m0, rsIn, k0, Kpad, tid);
                cp_tile_bf16(nb+30720, Xlb, m0, rsIn, k0, Kpad, tid);
            }
            CP_COMMIT();
            CP_WAIT1();
        } else {
            CP_WAIT0();
        }
        __syncthreads();
        unsigned bhB = diag ? cb+0     : cb+20480;
        unsigned blB = diag ? cb+10240 : cb+30720;
        gemm_chunk(acc, cb+0, cb+10240, bhB, blB, wm, wn, lane);
        __syncthreads();
    }

    const float* xxb = xx + b*N_;
    unsigned* sK = (unsigned*)smem;     /* 128x128 keys, pitch 129 words */
    int rr = lane>>2, cc = 2*(lane&3);
    #pragma unroll
    for(int mt=0;mt<4;mt++){
        int row = wm + mt*16 + rr;
        float xn0 = xxb[n0+row], xn8 = xxb[n0+row+8];
        #pragma unroll
        for(int nt=0;nt<4;nt++){
            int col = wn + nt*8 + cc;
            float xm0 = xxb[m0+col], xm1 = xxb[m0+col+1];
            uint2 u0, u1;
            u0.x = mkkey(2.f*acc[mt][nt][0] - xn0 - xm0);
            u0.y = mkkey(2.f*acc[mt][nt][1] - xn0 - xm1);
            u1.x = mkkey(2.f*acc[mt][nt][2] - xn8 - xm0);
            u1.y = mkkey(2.f*acc[mt][nt][3] - xn8 - xm1);
            if(diag){
                if(row   == col  ) u0.x = 0u;
                if(row   == col+1) u0.y = 0u;
                if(row+8 == col  ) u1.x = 0u;
                if(row+8 == col+1) u1.y = 0u;
            }
            *(uint2*)(pdk + ((size_t)b*N_ + n0+row  )*N_ + m0 + col) = u0;
            *(uint2*)(pdk + ((size_t)b*N_ + n0+row+8)*N_ + m0 + col) = u1;
            if(!diag){
                sK[ row   *129 + col  ] = u0.x;
                sK[ row   *129 + col+1] = u0.y;
                sK[(row+8)*129 + col  ] = u1.x;
                sK[(row+8)*129 + col+1] = u1.y;
            }
        }
    }
    if(!diag){
        __syncthreads();
        for(int i=0;i<16;i++){
            int r2 = wid + 8*i;
            size_t obase = ((size_t)b*N_ + m0 + r2)*N_ + n0;
            #pragma unroll
            for(int j=0;j<4;j++){
                int c2 = lane + 32*j;
                pdk[obase + c2] = sK[c2*129 + r2];
            }
        }
    }
}

/* ------- top-20 per row, 4-level 8-bit radix select on precomputed keys ---- */
__global__ void k_topk(const unsigned* __restrict__ pdk, int* __restrict__ idx){
    __shared__ unsigned hist[8][256];
    __shared__ unsigned sgs[256];
    __shared__ unsigned wtot[8], wabove[8];
    __shared__ int s_bin, s_above, s_outc, s_tiec;
    __shared__ int ties[2048];

    int b = blockIdx.y, n = blockIdx.x;
    int tid = threadIdx.x, lane = tid & 31, wp = tid >> 5;
    const unsigned* row = pdk + ((size_t)b*N_ + n)*N_;

    unsigned key[8];
    #pragma unroll
    for(int j=0;j<8;j++) key[j] = row[tid + 256*j];   /* self already 0 */

    unsigned prefix = 0, pmask = 0;
    int kneed = KNN;
    for(int level=0; level<4; level++){
        int shift = 24 - 8*level;
        #pragma unroll
        for(int w=0;w<8;w++) hist[w][tid] = 0;
        __syncthreads();
        #pragma unroll
        for(int j=0;j<8;j++){
            unsigned kk = key[j];
            if((kk & pmask) == prefix)
                atomicAdd(&hist[wp][(kk>>shift)&255u], 1u);
        }
        __syncthreads();
        unsigned c = 0;
        #pragma unroll
        for(int w=0;w<8;w++) c += hist[w][tid];
        unsigned s = c;
        #pragma unroll
        for(int off=1; off<32; off<<=1){
            unsigned o2 = __shfl_down_sync(0xffffffffu, s, off);
            if(lane + off < 32) s += o2;
        }
        if(lane==0) wtot[wp] = s;
        __syncthreads();
        if(tid==0){
            unsigned run=0;
            for(int w=7;w>=0;w--){ wabove[w]=run; run+=wtot[w]; }
        }
        __syncthreads();
        unsigned S = s + wabove[wp];
        sgs[tid] = S;
        __syncthreads();
        unsigned Snext = (tid<255) ? sgs[tid+1] : 0u;
        if(S >= (unsigned)kneed && Snext < (unsigned)kneed){
            s_bin = tid; s_above = (int)Snext;
        }
        __syncthreads();
        prefix |= ((unsigned)s_bin) << shift;
        pmask  |= 0xFFu << shift;
        kneed  -= s_above;
        __syncthreads();
    }

    unsigned T = prefix;
    int rem = kneed;                      /* # of ==T to take, >=1 */
    int* op = idx + ((b*N_)+n)*KNN;
    if(tid==0){ s_outc = 0; s_tiec = 0; }
    __syncthreads();
    #pragma unroll
    for(int j=0;j<8;j++){
        unsigned kk = key[j]; int m = tid + 256*j;
        if(kk > T){
            int p = atomicAdd(&s_outc, 1);
            op[p] = m;
        } else if(kk == T){
            int p = atomicAdd(&s_tiec, 1);
            ties[p] = m;
        }
    }
    __syncthreads();
    int cg = s_outc;
    if(wp==0){
        int tc = s_tiec;
        for(int r=0;r<rem;r++){
            int best = 0x7fffffff, bpos = -1;
            for(int t2=lane; t2<tc; t2+=32){
                int v = ties[t2];
                if(v < best){ best = v; bpos = t2; }
            }
            #pragma unroll
            for(int off=16; off>0; off>>=1){
                int ov = __shfl_xor_sync(0xffffffffu, best, off);
                int opo= __shfl_xor_sync(0xffffffffu, bpos, off);
                if(ov < best){ best = ov; bpos = opo; }
            }
            if(lane==0){ op[cg + r] = best; ties[bpos] = 0x7fffffff; }
            __syncwarp();
        }
    }
}

/* -------- conv1x1 (+BN+lrelu), pre-split bf16 weights; emits bf16 twins ---- */
__global__ __launch_bounds__(256,2) void k_conv_mma(
        const __nv_bfloat16* __restrict__ Wh, const __nv_bfloat16* __restrict__ Wl, int rsW,
        const float* __restrict__ gg, const float* __restrict__ bb,
        const __nv_bfloat16* __restrict__ Hh, const __nv_bfloat16* __restrict__ Hl,
        int rsB, int Kpad, int O,
        float* __restrict__ yout, int rsOut, int oOff,
        __nv_bfloat16* __restrict__ couth, __nv_bfloat16* __restrict__ coutl, int wbf){
    extern __shared__ char smem[];
    unsigned sb = smem_u32(smem);
    int b = blockIdx.z, n0 = blockIdx.x*128, o0 = blockIdx.y*128;
    int tid = threadIdx.x, wid = tid>>5, lane = tid&31;
    const __nv_bfloat16* Hhb = Hh + (size_t)b*N_*rsB;
    const __nv_bfloat16* Hlb = Hl + (size_t)b*N_*rsB;

    float acc[4][4][4];
    #pragma unroll
    for(int a=0;a<4;a++) for(int bq=0;bq<4;bq++) for(int cq=0;cq<4;cq++) acc[a][bq][cq]=0.f;

    int nch = (Kpad + KCH - 1)/KCH;
    cp_tile_bf16(sb+0,     Wh,  o0, rsW, 0, Kpad, tid);
    cp_tile_bf16(sb+10240, Wl,  o0, rsW, 0, Kpad, tid);
    cp_tile_bf16(sb+20480, Hhb, n0, rsB, 0, Kpad, tid);
    cp_tile_bf16(sb+30720, Hlb, n0, rsB, 0, Kpad, tid);
    CP_COMMIT();

    int wm = (wid>>2)*64, wn = (wid&3)*32;
    for(int c=0;c<nch;c++){
        unsigned cb = sb + (unsigned)((c&1)*STG);
        if(c+1 < nch){
            unsigned nb = sb + (unsigned)(((c+1)&1)*STG);
            int k0 = (c+1)*KCH;
            cp_tile_bf16(nb+0,     Wh,  o0, rsW, k0, Kpad, tid);
            cp_tile_bf16(nb+10240, Wl,  o0, rsW, k0, Kpad, tid);
            cp_tile_bf16(nb+20480, Hhb, n0, rsB, k0, Kpad, tid);
            cp_tile_bf16(nb+30720, Hlb, n0, rsB, k0, Kpad, tid);
            CP_COMMIT();
            CP_WAIT1();
        } else {
            CP_WAIT0();
        }
        __syncthreads();
        gemm_chunk(acc, cb+0, cb+10240, cb+20480, cb+30720, wm, wn, lane);
        __syncthreads();
    }

    float* sC = (float*)smem;
    int rr = lane>>2, cc = 2*(lane&3);
    #pragma unroll
    for(int mt=0;mt<4;mt++){
        int row = wm + mt*16 + rr;
        #pragma unroll
        for(int nt=0;nt<4;nt++){
            int col = wn + nt*8 + cc;
            sC[ row   *129 + col  ] = acc[mt][nt][0];
            sC[ row   *129 + col+1] = acc[mt][nt][1];
            sC[(row+8)*129 + col  ] = acc[mt][nt][2];
            sC[(row+8)*129 + col+1] = acc[mt][nt][3];
        }
    }
    __syncthreads();

    int Olocal = O - o0; if(Olocal > 128) Olocal = 128;
    float scv[4], bsv[4];
    #pragma unroll
    for(int j=0;j<4;j++){
        int o = lane + 32*j;
        scv[j] = (o<Olocal) ? BNS*gg[o0+o] : 0.f;
        bsv[j] = (o<Olocal) ? bb[o0+o]     : 0.f;
    }
    for(int i=0;i<16;i++){
        int n = wid + 8*i;
        size_t rbase = (size_t)(b*N_ + n0 + n);
        #pragma unroll
        for(int j=0;j<4;j++){
            int o = lane + 32*j;
            if(o < Olocal){
                float y = lrelu(fmaf(sC[o*129+n], scv[j], bsv[j]));
                yout[rbase*rsOut + oOff + o0 + o] = y;
                if(wbf){
                    __nv_bfloat16 h = __float2bfloat16(y);
                    couth[rbase*512 + oOff + o0 + o] = h;
                    coutl[rbase*512 + oOff + o0 + o] = __float2bfloat16(y - __bfloat162float(h));
                }
            }
        }
    }
}

/* ---- attention aggregate: writes bf16 hi/lo h = [q, softmax.(key-q)] ------ */
__global__ void k_attn(const float* __restrict__ xt, int C, int rs,
                       const int* __restrict__ idx,
                       __nv_bfloat16* __restrict__ hH, __nv_bfloat16* __restrict__ hL,
                       int rsH){
    int b    = blockIdx.y;
    int warp = threadIdx.x >> 5, lane = threadIdx.x & 31;
    int n    = blockIdx.x*8 + warp;
    const float* Xb = xt + (size_t)b*N_*rs;
    float q[4];
    #pragma unroll
    for(int j=0;j<4;j++){
        int c = lane + 32*j;
        q[j] = (c<C) ? Xb[(size_t)n*rs + c] : 0.f;
    }
    const int* ip = idx + ((b*N_)+n)*KNN;
    int   nbr[KNN];
    float lg [KNN];
    for(int k=0;k<KNN;k++){
        int m = ip[k];
        nbr[k] = m;
        const float* kp = Xb + (size_t)m*rs;
        float p = 0.f;
        #pragma unroll
        for(int j=0;j<4;j++){
            int c = lane + 32*j;
            if(c<C) p += q[j]*kp[c];
        }
        #pragma unroll
        for(int o=16;o>0;o>>=1) p += __shfl_xor_sync(0xffffffffu,p,o);
        lg[k] = p;
    }
    float mx = -3e38f;
    #pragma unroll
    for(int k=0;k<KNN;k++) mx = fmaxf(mx, lg[k]);
    float Z = 0.f;
    #pragma unroll
    for(int k=0;k<KNN;k++){ lg[k] = expf(lg[k]-mx); Z += lg[k]; }
    float inv = 1.f/Z;
    size_t base = (size_t)(b*N_+n)*rsH;
    #pragma unroll
    for(int j=0;j<4;j++){
        int c = lane + 32*j;
        if(c<C){
            float f = 0.f;
            for(int k=0;k<KNN;k++) f += lg[k]*(Xb[(size_t)nbr[k]*rs + c] - q[j]);
            f *= inv;
            __nv_bfloat16 qh = __float2bfloat16(q[j]);
            hH[base + c]   = qh;
            hL[base + c]   = __float2bfloat16(q[j] - __bfloat162float(qh));
            __nv_bfloat16 fh = __float2bfloat16(f);
            hH[base + C + c] = fh;
            hL[base + C + c] = __float2bfloat16(f - __bfloat162float(fh));
        }
    }
    int extra = rsH - 2*C;
    if(extra > 0 && lane < extra){
        hH[base + 2*C + lane] = __float2bfloat16(0.f);
        hL[base + 2*C + lane] = __float2bfloat16(0.f);
    }
}

/* ------------ scores[b,n,h] = lrelu(sum_e x5[b,n,e] Watt[h,e]) ------------- */
__global__ void k_scores(const float* __restrict__ x5, const float* __restrict__ Watt,
                         float* __restrict__ sc){
    int gw   = (blockIdx.x*256 + threadIdx.x) >> 5;
    int lane = threadIdx.x & 31;
    if(gw >= B_*N_) return;
    const float* xp = x5 + (size_t)gw*1024;
    float a0=0,a1=0,a2=0,a3=0;
    for(int e=lane;e<1024;e+=32){
        float v = xp[e];
        a0 += v*Watt[e];
        a1 += v*Watt[1024+e];
        a2 += v*Watt[2048+e];
        a3 += v*Watt[3072+e];
    }
    #pragma unroll
    for(int o=16;o>0;o>>=1){
        a0 += __shfl_xor_sync(0xffffffffu,a0,o);
        a1 += __shfl_xor_sync(0xffffffffu,a1,o);
        a2 += __shfl_xor_sync(0xffffffffu,a2,o);
        a3 += __shfl_xor_sync(0xffffffffu,a3,o);
    }
    if(lane==0){
        sc[(size_t)gw*4+0] = lrelu(a0);
        sc[(size_t)gw*4+1] = lrelu(a1);
        sc[(size_t)gw*4+2] = lrelu(a2);
        sc[(size_t)gw*4+3] = lrelu(a3);
    }
}

/* --- attp[seg,b,h*1024+e] = sum_{n in seg} x5[b,n,e]*sc[b,n,h], 8 segs ----- */
__global__ void k_attagg(const float* __restrict__ x5, const float* __restrict__ sc,
                         float* __restrict__ attp){
    __shared__ float ssc[256*4];
    int b = blockIdx.y, seg = blockIdx.z;
    int e = blockIdx.x*256 + threadIdx.x;
    int n0 = seg*256;
    float a0=0,a1=0,a2=0,a3=0;
    for(int i=threadIdx.x;i<1024;i+=256)
        ssc[i] = sc[((size_t)b*N_+n0)*4 + i];
    __syncthreads();
    for(int nn=0;nn<256;nn++){
        float v = x5[((size_t)(b*N_+n0+nn))*1024 + e];
        a0 += v*ssc[nn*4+0];
        a1 += v*ssc[nn*4+1];
        a2 += v*ssc[nn*4+2];
        a3 += v*ssc[nn*4+3];
    }
    float* op = attp + ((size_t)seg*B_ + b)*4096;
    op[   0 + e] = a0;
    op[1024 + e] = a1;
    op[2048 + e] = a2;
    op[3072 + e] = a3;
}

/* ------------- LayerNorm(4096) over summed partials + lrelu ---------------- */
__global__ void k_ln(const float* __restrict__ attp, const float* __restrict__ g,
                     const float* __restrict__ bt, float* __restrict__ out){
    __shared__ float red[256];
    __shared__ float sv[4096];
    int b = blockIdx.x, tid = threadIdx.x;
    float s=0.f;
    for(int i=tid;i<4096;i+=256){
        float a = 0.f;
        #pragma unroll
        for(int seg=0;seg<NSEG;seg++)
            a += attp[((size_t)seg*B_ + b)*4096 + i];
        sv[i] = a;
        s += a;
    }
    red[tid]=s; __syncthreads();
    for(int st=128;st>0;st>>=1){ if(tid<st) red[tid]+=red[tid+st]; __syncthreads(); }
    float mean = red[0]*(1.f/4096.f); __syncthreads();
    float v=0.f;
    for(int i=tid;i<4096;i+=256){ float d=sv[i]-mean; v+=d*d; }
    red[tid]=v; __syncthreads();
    for(int st=128;st>0;st>>=1){ if(tid<st) red[tid]+=red[tid+st]; __syncthreads(); }
    float inv = 1.f/sqrtf(red[0]*(1.f/4096.f) + LNEPS);
    for(int i=tid;i<4096;i+=256){
        float y = (sv[i]-mean)*inv*g[i] + bt[i];
        out[b*4096+i] = lrelu(y);
    }
}

/* ------------- warp-per-output fully-connected (+opt bnaff+lrelu) ---------- */
__global__ void k_fc(const float* __restrict__ A, const float* __restrict__ W,
                     const float* __restrict__ bias, const float* __restrict__ g,
                     const float* __restrict__ bt, float* __restrict__ out,
                     int K, int O, int mode){
    int gw   = (blockIdx.x*256 + threadIdx.x) >> 5;
    int lane = threadIdx.x & 31;
    if(gw >= B_*O) return;
    int b = gw / O, o = gw % O;
    const float* a = A + (size_t)b*K;
    const float* w = W + (size_t)o*K;
    float s=0.f;
    for(int k2=lane;k2<K;k2+=32) s += a[k2]*w[k2];
    #pragma unroll
    for(int off=16;off>0;off>>=1) s += __shfl_xor_sync(0xffffffffu,s,off);
    if(lane==0){
        s += bias[o];
        if(mode){ s = s*BNS*g[o] + bt[o]; s = lrelu(s); }
        out[(size_t)b*O+o] = s;
    }
}

/* ------------------------------- launcher ---------------------------------- */
extern "C" void kernel_launch(void* const* d_in, const int* in_sizes, int n_in,
                              void* d_out, int out_size){
    const float* x    = (const float*)d_in[0];
    const float* W1   = (const float*)d_in[1];
    const float* g1   = (const float*)d_in[2];
    const float* b1   = (const float*)d_in[3];
    const float* W2   = (const float*)d_in[4];
    const float* g2   = (const float*)d_in[5];
    const float* b2   = (const float*)d_in[6];
    const float* W3   = (const float*)d_in[7];
    const float* g3   = (const float*)d_in[8];
    const float* b3   = (const float*)d_in[9];
    const float* W4   = (const float*)d_in[10];
    const float* g4   = (const float*)d_in[11];
    const float* b4   = (const float*)d_in[12];
    const float* W5   = (const float*)d_in[13];
    const float* g5   = (const float*)d_in[14];
    const float* b5   = (const float*)d_in[15];
    const float* Watt = (const float*)d_in[16];
    const float* ln_g = (const float*)d_in[17];
    const float* ln_b = (const float*)d_in[18];
    const float* Wl1  = (const float*)d_in[19];
    const float* bl1  = (const float*)d_in[20];
    const float* g6   = (const float*)d_in[21];
    const float* b6   = (const float*)d_in[22];
    const float* Wl2  = (const float*)d_in[23];
    const float* bl2  = (const float*)d_in[24];
    const float* g7   = (const float*)d_in[25];
    const float* b7   = (const float*)d_in[26];
    const float* Wl3  = (const float*)d_in[27];
    const float* bl3  = (const float*)d_in[28];

    float *xt, *cat, *x5, *xx, *sc, *attp, *attln, *y1, *y2;
    unsigned* pdk;
    int* idx;
    __nv_bfloat16 *xth, *xtl, *hh, *hl, *cath, *catl;
    __nv_bfloat16 *w1h,*w1l,*w2h,*w2l,*w3h,*w3l,*w4h,*w4l,*w5h,*w5l;
    cudaGetSymbolAddress((void**)&xt,   g_xt);
    cudaGetSymbolAddress((void**)&cat,  g_cat);
    cudaGetSymbolAddress((void**)&x5,   g_x5);
    cudaGetSymbolAddress((void**)&pdk,  g_pd);
    cudaGetSymbolAddress((void**)&xx,   g_xx);
    cudaGetSymbolAddress((void**)&idx,  g_idx);
    cudaGetSymbolAddress((void**)&sc,   g_sc);
    cudaGetSymbolAddress((void**)&attp, g_attp);
    cudaGetSymbolAddress((void**)&attln,g_attln);
    cudaGetSymbolAddress((void**)&y1,   g_y1);
    cudaGetSymbolAddress((void**)&y2,   g_y2);
    cudaGetSymbolAddress((void**)&xth,  g_xth);
    cudaGetSymbolAddress((void**)&xtl,  g_xtl);
    cudaGetSymbolAddress((void**)&hh,   g_hh);
    cudaGetSymbolAddress((void**)&hl,   g_hl);
    cudaGetSymbolAddress((void**)&cath, g_cath);
    cudaGetSymbolAddress((void**)&catl, g_catl);
    cudaGetSymbolAddress((void**)&w1h,  g_w1h);
    cudaGetSymbolAddress((void**)&w1l,  g_w1l);
    cudaGetSymbolAddress((void**)&w2h,  g_w2h);
    cudaGetSymbolAddress((void**)&w2l,  g_w2l);
    cudaGetSymbolAddress((void**)&w3h,  g_w3h);
    cudaGetSymbolAddress((void**)&w3l,  g_w3l);
    cudaGetSymbolAddress((void**)&w4h,  g_w4h);
    cudaGetSymbolAddress((void**)&w4l,  g_w4l);
    cudaGetSymbolAddress((void**)&w5h,  g_w5h);
    cudaGetSymbolAddress((void**)&w5l,  g_w5l);

    cudaFuncSetAttribute(k_pd_mma,   cudaFuncAttributeMaxDynamicSharedMemorySize, SMEMB);
    cudaFuncSetAttribute(k_conv_mma, cudaFuncAttributeMaxDynamicSharedMemorySize, SMEMB);

    /* weight pre-split (padded Opad x rsW) */
    k_wsplit<<<(128*32  + 255)/256, 256>>>(W1,   64,   6, 128,  32, w1h, w1l);
    k_wsplit<<<(128*128 + 255)/256, 256>>>(W2,   64, 128, 128, 128, w2h, w2l);
    k_wsplit<<<(128*128 + 255)/256, 256>>>(W3,  128, 128, 128, 128, w3h, w3l);
    k_wsplit<<<(256*256 + 255)/256, 256>>>(W4,  256, 256, 256, 256, w4h, w4l);
    k_wsplit<<<(1024*512+ 255)/256, 256>>>(W5, 1024, 512,1024, 512, w5h, w5l);

    k_transpose_in<<<(B_*N_)/256, 256>>>(x, xt, xth, xtl);

    auto stage = [&](const float* XinF, int rsF,
                     const __nv_bfloat16* Xh, const __nv_bfloat16* Xl, int rsBf, int Kpad,
                     int C, const __nv_bfloat16* Wch, const __nv_bfloat16* Wcl, int rsW,
                     const float* gc, const float* bc,
                     int O, int rsH, int oOff){
        k_xx<<<(B_*N_)/256, 256>>>(XinF, C, rsF, xx);
        k_pd_mma<<<dim3(NTRI, 1, B_), 256, SMEMB>>>(Xh, Xl, rsBf, Kpad, xx, pdk);
        k_topk<<<dim3(N_, B_), 256>>>(pdk, idx);
        k_attn<<<dim3(N_/8, B_), 256>>>(XinF, C, rsF, idx, hh, hl, rsH);
        k_conv_mma<<<dim3(N_/128, (O+127)/128, B_), 256, SMEMB>>>(
            Wch, Wcl, rsW, gc, bc, hh, hl, rsH, rsH, O, cat, 512, oOff, cath, catl, 1);
    };

    stage(xt,        3,   xth,      xtl,      16,  16,  3,
          w1h, w1l, 32,  g1, b1,  64,  16,   0);
    stage(cat +   0, 512, cath+0,   catl+0,   512, 64,  64,
          w2h, w2l, 128, g2, b2,  64,  128,  64);
    stage(cat +  64, 512, cath+64,  catl+64,  512, 64,  64,
          w3h, w3l, 128, g3, b3, 128,  128, 128);
    stage(cat + 128, 512, cath+128, catl+128, 512, 128, 128,
          w4h, w4l, 256, g4, b4, 256,  256, 256);

    /* x5 = conv_bn(concat, W5) : C2=512, O=1024 */
    k_conv_mma<<<dim3(N_/128, 1024/128, B_), 256, SMEMB>>>(
        w5h, w5l, 512, g5, b5, cath, catl, 512, 512, 1024, x5, 1024, 0,
        (__nv_bfloat16*)0, (__nv_bfloat16*)0, 0);

    k_scores<<<(B_*N_)/8, 256>>>(x5, Watt, sc);
    k_attagg<<<dim3(1024/256, B_, NSEG), 256>>>(x5, sc, attp);
    k_ln<<<B_, 256>>>(attp, ln_g, ln_b, attln);

    k_fc<<<(B_*512)/8, 256>>>(attln, Wl1, bl1, g6, b6, y1, 4096, 512, 1);
    k_fc<<<(B_*256)/8, 256>>>(y1,    Wl2, bl2, g7, b7, y2,  512, 256, 1);
    k_fc<<<(B_*40 + 7)/8, 256>>>(y2, Wl3, bl3, (const float*)0, (const float*)0,
                                 (float*)d_out, 256, 40, 0);
}